// round 11
// baseline (speedup 1.0000x reference)
#include <cuda_runtime.h>
#include <cuda_bf16.h>
#include <cstdint>
#include <math.h>

#define SEQ     1024
#define INPUT_D 512
#define HID     1024
#define GATES_N 4096
#define STEPS   128
#define OUT_D   1000

// ---------------- device scratch (total ~2.5 GB, under aarch64 ADRP limit) ---
__device__ __nv_bfloat16 g_xhi[(size_t)STEPS * SEQ * INPUT_D];   // 134 MB
__device__ __nv_bfloat16 g_xlo[(size_t)STEPS * SEQ * INPUT_D];   // 134 MB
__device__ __nv_bfloat16 g_wxh[2][GATES_N * INPUT_D];            // gate-interleaved rows
__device__ __nv_bfloat16 g_wxl[2][GATES_N * INPUT_D];
__device__ __nv_bfloat16 g_whh[2][GATES_N * HID];
__device__ __nv_bfloat16 g_whl[2][GATES_N * HID];
__device__ float g_bias[2][GATES_N];                             // permuted b_ih + b_hh
__device__ float g_gx1[(size_t)STEPS * SEQ * GATES_N];           // L1 x-gates (2.15 GB)
__device__ __nv_bfloat16 g_hhi[SEQ * HID];
__device__ __nv_bfloat16 g_hlo[SEQ * HID];
__device__ float g_c[SEQ * HID];
__device__ float g_gates[(size_t)SEQ * GATES_N];                 // interleaved gates
__device__ float g_hlast[STEPS * HID];

// ---------------- helpers ----------------
__device__ __forceinline__ uint32_t smem_u32(const void* p) {
    return (uint32_t)__cvta_generic_to_shared(p);
}
__device__ __forceinline__ void cp16(uint32_t saddr, const void* gaddr) {
    asm volatile("cp.async.cg.shared.global [%0], [%1], 16;" :: "r"(saddr), "l"(gaddr) : "memory");
}
#define CP_COMMIT() asm volatile("cp.async.commit_group;" ::: "memory")
#define CP_WAIT(n)  asm volatile("cp.async.wait_group %0;" :: "n"(n) : "memory")

__device__ __forceinline__ uint32_t sw128(uint32_t off) {
    return off ^ ((off >> 3) & 0x70);
}

#define TILE_M   128
#define TILE_N   128
#define CHUNK_K  64
#define NS       3
#define A_BYTES  (TILE_M * CHUNK_K * 2)      // 16 KB
#define STAGE_BYTES (2 * A_BYTES)            // 32 KB
#define SMEM_DYN (NS * STAGE_BYTES)          // 96 KB -> 2 CTAs/SM

#define MMA_TILE_BODY(BF_SRC) \
    asm volatile( \
        "mma.sync.aligned.m16n8k16.row.col.f32.bf16.bf16.f32 " \
        "{%0,%1,%2,%3}, {%4,%5,%6,%7}, {%8,%9}, {%0,%1,%2,%3};" \
        : "+f"(acc[mt][nt][0]), "+f"(acc[mt][nt][1]), \
          "+f"(acc[mt][nt][2]), "+f"(acc[mt][nt][3]) \
        : "r"(a0), "r"(a1), "r"(a2), "r"(a3), \
          "r"(BF_SRC[nt][0]), "r"(BF_SRC[nt][1]));

// ---------------- precompute kernel: gx1 = x @ Wx1^T + bias1 (all steps) -----
#define XCHUNKS 24     // 3 products x (512/64)

__global__ __launch_bounds__(256, 2)
void gemm_x_all(const __nv_bfloat16* __restrict__ xhi_all, const __nv_bfloat16* __restrict__ xlo_all,
                const __nv_bfloat16* __restrict__ wxh, const __nv_bfloat16* __restrict__ wxl,
                const float* __restrict__ bsum,
                float* __restrict__ gx1)
{
    extern __shared__ __align__(1024) char smem_raw[];
    const uint32_t sbase = smem_u32(smem_raw);

    const int tid = threadIdx.x;
    const int wid = tid >> 5;
    const int lane = tid & 31;
    const int wm = wid & 1;
    const int wn = wid >> 1;
    const int bn = blockIdx.x * TILE_N;
    const int bm = blockIdx.y * TILE_M;
    const int step = blockIdx.z;

    const __nv_bfloat16* xhi = xhi_all + (size_t)step * SEQ * INPUT_D;
    const __nv_bfloat16* xlo = xlo_all + (size_t)step * SEQ * INPUT_D;
    float* out = gx1 + (size_t)step * SEQ * GATES_N;

    const int lrow = tid >> 3;
    const int lcol = (tid & 7) * 16;
    auto load_chunk = [&](int cc, int stage) {
        const int prod = cc >> 3;
        const int k0 = (cc & 7) * CHUNK_K;
        const __nv_bfloat16* a = (prod == 2) ? xlo : xhi;
        const __nv_bfloat16* b = (prod == 1) ? wxl : wxh;
        const uint32_t abase = sbase + stage * STAGE_BYTES;
        const uint32_t bbase = abase + A_BYTES;
#pragma unroll
        for (int v = 0; v < 4; v++) {
            const int row = v * 32 + lrow;
            cp16(abase + sw128(row * 128 + lcol),
                 a + (size_t)(bm + row) * INPUT_D + k0 + lcol / 2);
            cp16(bbase + sw128(row * 128 + lcol),
                 b + (size_t)(bn + row) * INPUT_D + k0 + lcol / 2);
        }
    };

    float acc[4][4][4];
#pragma unroll
    for (int i = 0; i < 4; i++)
#pragma unroll
        for (int j = 0; j < 4; j++)
#pragma unroll
            for (int q = 0; q < 4; q++) acc[i][j][q] = 0.0f;

    auto compute_chunk = [&](int stage) {
        const uint32_t abase = sbase + stage * STAGE_BYTES;
        const uint32_t bbase = abase + A_BYTES;
#pragma unroll
        for (int ks = 0; ks < 4; ks++) {
            uint32_t bf[4][2];
#pragma unroll
            for (int ntp = 0; ntp < 2; ntp++) {
                const int g = lane >> 3, l7 = lane & 7;
                const int nrow = wn * 32 + ntp * 16 + ((g >> 1) << 3) + l7;
                const uint32_t addr = bbase + sw128(nrow * 128 + ks * 32 + (g & 1) * 16);
                asm volatile("ldmatrix.sync.aligned.m8n8.x4.shared.b16 {%0,%1,%2,%3}, [%4];"
                    : "=r"(bf[ntp * 2][0]), "=r"(bf[ntp * 2][1]),
                      "=r"(bf[ntp * 2 + 1][0]), "=r"(bf[ntp * 2 + 1][1])
                    : "r"(addr));
            }
#pragma unroll
            for (int mt = 0; mt < 4; mt++) {
                const int mrow = wm * 64 + mt * 16 + (lane & 15);
                const uint32_t aaddr = abase + sw128(mrow * 128 + ks * 32 + (lane >> 4) * 16);
                uint32_t a0, a1, a2, a3;
                asm volatile("ldmatrix.sync.aligned.m8n8.x4.shared.b16 {%0,%1,%2,%3}, [%4];"
                    : "=r"(a0), "=r"(a1), "=r"(a2), "=r"(a3) : "r"(aaddr));
#pragma unroll
                for (int nt = 0; nt < 4; nt++) { MMA_TILE_BODY(bf) }
            }
        }
    };

#pragma unroll
    for (int p = 0; p < NS - 1; p++) { load_chunk(p, p); CP_COMMIT(); }
#pragma unroll 1
    for (int i = 0; i < XCHUNKS; i++) {
        CP_WAIT(NS - 2);
        __syncthreads();
        if (i + NS - 1 < XCHUNKS) load_chunk(i + NS - 1, (i + NS - 1) % NS);
        CP_COMMIT();
        compute_chunk(i % NS);
    }

#pragma unroll
    for (int mt = 0; mt < 4; mt++) {
        const int m0 = bm + wm * 64 + mt * 16 + (lane >> 2);
#pragma unroll
        for (int nt = 0; nt < 4; nt++) {
            const int n0 = bn + wn * 32 + nt * 8 + (lane & 3) * 2;
            float2 v0, v1;
            v0.x = acc[mt][nt][0] + bsum[n0]; v0.y = acc[mt][nt][1] + bsum[n0 + 1];
            v1.x = acc[mt][nt][2] + bsum[n0]; v1.y = acc[mt][nt][3] + bsum[n0 + 1];
            *reinterpret_cast<float2*>(out + (size_t)m0 * GATES_N + n0) = v0;
            *reinterpret_cast<float2*>(out + (size_t)(m0 + 8) * GATES_N + n0) = v1;
        }
    }
}

// ---------------- L1 per-step kernel: gates = h @ Wh1^T + gx1[t] -------------
#define HCHUNKS 48     // 3 products x (1024/64)

__global__ __launch_bounds__(256, 2)
void gemm_h(const __nv_bfloat16* __restrict__ hhi, const __nv_bfloat16* __restrict__ hlo,
            const __nv_bfloat16* __restrict__ whh, const __nv_bfloat16* __restrict__ whl,
            const float* __restrict__ gx,
            float* __restrict__ out)
{
    extern __shared__ __align__(1024) char smem_raw[];
    const uint32_t sbase = smem_u32(smem_raw);

    const int tid = threadIdx.x;
    const int wid = tid >> 5;
    const int lane = tid & 31;
    const int wm = wid & 1;
    const int wn = wid >> 1;
    const int bn = blockIdx.x * TILE_N;
    const int bm = blockIdx.y * TILE_M;

    cudaGridDependencySynchronize();     // h must be final (PDL)

    const int lrow = tid >> 3;
    const int lcol = (tid & 7) * 16;
    auto load_chunk = [&](int cc, int stage) {
        const int prod = cc >> 4;
        const int k0 = (cc & 15) * CHUNK_K;
        const __nv_bfloat16* a = (prod == 2) ? hlo : hhi;
        const __nv_bfloat16* b = (prod == 1) ? whl : whh;
        const uint32_t abase = sbase + stage * STAGE_BYTES;
        const uint32_t bbase = abase + A_BYTES;
#pragma unroll
        for (int v = 0; v < 4; v++) {
            const int row = v * 32 + lrow;
            cp16(abase + sw128(row * 128 + lcol),
                 a + (size_t)(bm + row) * HID + k0 + lcol / 2);
            cp16(bbase + sw128(row * 128 + lcol),
                 b + (size_t)(bn + row) * HID + k0 + lcol / 2);
        }
    };

    float acc[4][4][4];
#pragma unroll
    for (int i = 0; i < 4; i++)
#pragma unroll
        for (int j = 0; j < 4; j++)
#pragma unroll
            for (int q = 0; q < 4; q++) acc[i][j][q] = 0.0f;

    auto compute_chunk = [&](int stage) {
        const uint32_t abase = sbase + stage * STAGE_BYTES;
        const uint32_t bbase = abase + A_BYTES;
#pragma unroll
        for (int ks = 0; ks < 4; ks++) {
            uint32_t bf[4][2];
#pragma unroll
            for (int ntp = 0; ntp < 2; ntp++) {
                const int g = lane >> 3, l7 = lane & 7;
                const int nrow = wn * 32 + ntp * 16 + ((g >> 1) << 3) + l7;
                const uint32_t addr = bbase + sw128(nrow * 128 + ks * 32 + (g & 1) * 16);
                asm volatile("ldmatrix.sync.aligned.m8n8.x4.shared.b16 {%0,%1,%2,%3}, [%4];"
                    : "=r"(bf[ntp * 2][0]), "=r"(bf[ntp * 2][1]),
                      "=r"(bf[ntp * 2 + 1][0]), "=r"(bf[ntp * 2 + 1][1])
                    : "r"(addr));
            }
#pragma unroll
            for (int mt = 0; mt < 4; mt++) {
                const int mrow = wm * 64 + mt * 16 + (lane & 15);
                const uint32_t aaddr = abase + sw128(mrow * 128 + ks * 32 + (lane >> 4) * 16);
                uint32_t a0, a1, a2, a3;
                asm volatile("ldmatrix.sync.aligned.m8n8.x4.shared.b16 {%0,%1,%2,%3}, [%4];"
                    : "=r"(a0), "=r"(a1), "=r"(a2), "=r"(a3) : "r"(aaddr));
#pragma unroll
                for (int nt = 0; nt < 4; nt++) { MMA_TILE_BODY(bf) }
            }
        }
    };

#pragma unroll
    for (int p = 0; p < NS - 1; p++) { load_chunk(p, p); CP_COMMIT(); }
#pragma unroll 1
    for (int i = 0; i < HCHUNKS; i++) {
        CP_WAIT(NS - 2);
        __syncthreads();
        if (i + NS - 1 < HCHUNKS) load_chunk(i + NS - 1, (i + NS - 1) % NS);
        CP_COMMIT();
        compute_chunk(i % NS);
    }

#pragma unroll
    for (int mt = 0; mt < 4; mt++) {
        const int m0 = bm + wm * 64 + mt * 16 + (lane >> 2);
#pragma unroll
        for (int nt = 0; nt < 4; nt++) {
            const int n0 = bn + wn * 32 + nt * 8 + (lane & 3) * 2;
            const float2 x0 = *reinterpret_cast<const float2*>(gx + (size_t)m0 * GATES_N + n0);
            const float2 x1 = *reinterpret_cast<const float2*>(gx + (size_t)(m0 + 8) * GATES_N + n0);
            float2 v0, v1;
            v0.x = acc[mt][nt][0] + x0.x; v0.y = acc[mt][nt][1] + x0.y;
            v1.x = acc[mt][nt][2] + x1.x; v1.y = acc[mt][nt][3] + x1.y;
            *reinterpret_cast<float2*>(out + (size_t)m0 * GATES_N + n0) = v0;
            *reinterpret_cast<float2*>(out + (size_t)(m0 + 8) * GATES_N + n0) = v1;
        }
    }
    cudaTriggerProgrammaticLaunchCompletion();
}

// ---------------- L2 per-step kernel: full 72 chunks, x-first + PDL ----------
#define NCHUNKS  72
#define FIRST_H  24

__global__ __launch_bounds__(256, 2)
void gemm_xh(const __nv_bfloat16* __restrict__ xhi, const __nv_bfloat16* __restrict__ xlo,
             const __nv_bfloat16* __restrict__ hhi, const __nv_bfloat16* __restrict__ hlo,
             const __nv_bfloat16* __restrict__ wxh, const __nv_bfloat16* __restrict__ wxl,
             const __nv_bfloat16* __restrict__ whh, const __nv_bfloat16* __restrict__ whl,
             const float* __restrict__ bsum,
             float* __restrict__ out)
{
    extern __shared__ __align__(1024) char smem_raw[];
    const uint32_t sbase = smem_u32(smem_raw);

    const int tid = threadIdx.x;
    const int wid = tid >> 5;
    const int lane = tid & 31;
    const int wm = wid & 1;
    const int wn = wid >> 1;
    const int bn = blockIdx.x * TILE_N;
    const int bm = blockIdx.y * TILE_M;

    auto get_src = [&](int cc, const __nv_bfloat16*& a, const __nv_bfloat16*& b,
                       int& k0, int& kst) {
        if (cc < FIRST_H) {
            const int prod = cc >> 3;
            kst = INPUT_D; k0 = (cc & 7) * CHUNK_K;
            a = (prod == 2) ? xlo : xhi;
            b = (prod == 1) ? wxl : wxh;
        } else {
            const int q = cc - FIRST_H;
            const int prod = q >> 4;
            kst = HID; k0 = (q & 15) * CHUNK_K;
            a = (prod == 2) ? hlo : hhi;
            b = (prod == 1) ? whl : whh;
        }
    };

    const int lrow = tid >> 3;
    const int lcol = (tid & 7) * 16;
    auto load_chunk = [&](int cc, int stage) {
        const __nv_bfloat16 *a, *b; int k0, kst;
        get_src(cc, a, b, k0, kst);
        const uint32_t abase = sbase + stage * STAGE_BYTES;
        const uint32_t bbase = abase + A_BYTES;
#pragma unroll
        for (int v = 0; v < 4; v++) {
            const int row = v * 32 + lrow;
            cp16(abase + sw128(row * 128 + lcol),
                 a + (size_t)(bm + row) * kst + k0 + lcol / 2);
            cp16(bbase + sw128(row * 128 + lcol),
                 b + (size_t)(bn + row) * kst + k0 + lcol / 2);
        }
    };

    float acc[4][4][4];
#pragma unroll
    for (int i = 0; i < 4; i++)
#pragma unroll
        for (int j = 0; j < 4; j++)
#pragma unroll
            for (int q = 0; q < 4; q++) acc[i][j][q] = 0.0f;

    auto compute_chunk = [&](int stage) {
        const uint32_t abase = sbase + stage * STAGE_BYTES;
        const uint32_t bbase = abase + A_BYTES;
#pragma unroll
        for (int ks = 0; ks < 4; ks++) {
            uint32_t bf[4][2];
#pragma unroll
            for (int ntp = 0; ntp < 2; ntp++) {
                const int g = lane >> 3, l7 = lane & 7;
                const int nrow = wn * 32 + ntp * 16 + ((g >> 1) << 3) + l7;
                const uint32_t addr = bbase + sw128(nrow * 128 + ks * 32 + (g & 1) * 16);
                asm volatile("ldmatrix.sync.aligned.m8n8.x4.shared.b16 {%0,%1,%2,%3}, [%4];"
                    : "=r"(bf[ntp * 2][0]), "=r"(bf[ntp * 2][1]),
                      "=r"(bf[ntp * 2 + 1][0]), "=r"(bf[ntp * 2 + 1][1])
                    : "r"(addr));
            }
#pragma unroll
            for (int mt = 0; mt < 4; mt++) {
                const int mrow = wm * 64 + mt * 16 + (lane & 15);
                const uint32_t aaddr = abase + sw128(mrow * 128 + ks * 32 + (lane >> 4) * 16);
                uint32_t a0, a1, a2, a3;
                asm volatile("ldmatrix.sync.aligned.m8n8.x4.shared.b16 {%0,%1,%2,%3}, [%4];"
                    : "=r"(a0), "=r"(a1), "=r"(a2), "=r"(a3) : "r"(aaddr));
#pragma unroll
                for (int nt = 0; nt < 4; nt++) { MMA_TILE_BODY(bf) }
            }
        }
    };

#pragma unroll
    for (int p = 0; p < NS - 1; p++) { load_chunk(p, p); CP_COMMIT(); }
#pragma unroll 1
    for (int i = 0; i < NCHUNKS; i++) {
        CP_WAIT(NS - 2);
        __syncthreads();
        const int nc = i + NS - 1;
        if (nc < NCHUNKS) {
            if (nc == FIRST_H)
                cudaGridDependencySynchronize();   // h final (cell1 done)
            load_chunk(nc, nc % NS);
        }
        CP_COMMIT();
        compute_chunk(i % NS);
    }

#pragma unroll
    for (int mt = 0; mt < 4; mt++) {
        const int m0 = bm + wm * 64 + mt * 16 + (lane >> 2);
#pragma unroll
        for (int nt = 0; nt < 4; nt++) {
            const int n0 = bn + wn * 32 + nt * 8 + (lane & 3) * 2;
            float2 v0, v1;
            v0.x = acc[mt][nt][0] + bsum[n0]; v0.y = acc[mt][nt][1] + bsum[n0 + 1];
            v1.x = acc[mt][nt][2] + bsum[n0]; v1.y = acc[mt][nt][3] + bsum[n0 + 1];
            *reinterpret_cast<float2*>(out + (size_t)m0 * GATES_N + n0) = v0;
            *reinterpret_cast<float2*>(out + (size_t)(m0 + 8) * GATES_N + n0) = v1;
        }
    }
    cudaTriggerProgrammaticLaunchCompletion();
}

// ---------------- pointwise kernels ----------------
__global__ void split_kernel(const float* __restrict__ src, __nv_bfloat16* __restrict__ hi,
                             __nv_bfloat16* __restrict__ lo, size_t n, float scale)
{
    const size_t i = (size_t)blockIdx.x * blockDim.x + threadIdx.x;
    if (i < n) {
        const float v = src[i] * scale;
        const __nv_bfloat16 h = __float2bfloat16(v);
        hi[i] = h;
        lo[i] = __float2bfloat16(v - __bfloat162float(h));
    }
}

__global__ void split_permute_w(const float* __restrict__ src, __nv_bfloat16* __restrict__ hi,
                                __nv_bfloat16* __restrict__ lo, int kshift)
{
    const size_t i = (size_t)blockIdx.x * blockDim.x + threadIdx.x;
    const int K = 1 << kshift;
    if (i < (size_t)GATES_N << kshift) {
        const int row = (int)(i >> kshift);
        const int k = (int)(i & (K - 1));
        const int nrow = ((row & 1023) << 2) | (row >> 10);
        const float v = src[i];
        const __nv_bfloat16 h = __float2bfloat16(v);
        hi[(size_t)nrow * K + k] = h;
        lo[(size_t)nrow * K + k] = __float2bfloat16(v - __bfloat162float(h));
    }
}

__global__ void bias_combine(const float* __restrict__ b_ih, const float* __restrict__ b_hh,
                             float* __restrict__ bsum)
{
    const int i = blockIdx.x * blockDim.x + threadIdx.x;
    if (i < GATES_N) {
        const int ni = ((i & 1023) << 2) | (i >> 10);
        bsum[ni] = b_ih[i] + b_hh[i];
    }
}

__global__ void zero_state_kernel()
{
    const int i = blockIdx.x * blockDim.x + threadIdx.x;
    if (i < SEQ * HID) {
        g_hhi[i] = __float2bfloat16(0.f);
        g_hlo[i] = __float2bfloat16(0.f);
        g_c[i] = 0.f;
    }
}

__global__ __launch_bounds__(256)
void lstm_cell_kernel(const float* __restrict__ gates,   // interleaved [m][4u+g]
                      __nv_bfloat16* __restrict__ hhi, __nv_bfloat16* __restrict__ hlo,
                      float* __restrict__ c, float* __restrict__ hlast)
{
    cudaGridDependencySynchronize();
    const int idx = blockIdx.x * blockDim.x + threadIdx.x;   // m*1024 + u
    const float4 g4 = reinterpret_cast<const float4*>(gates)[idx];

    const float si = 1.0f / (1.0f + expf(-g4.x));
    const float sf = 1.0f / (1.0f + expf(-g4.y));
    const float tg = tanhf(g4.z);
    const float so = 1.0f / (1.0f + expf(-g4.w));

    const float cn = sf * c[idx] + si * tg;
    const float hn = so * tanhf(cn);
    c[idx] = cn;

    const __nv_bfloat16 hh = __float2bfloat16(hn);
    hhi[idx] = hh;
    hlo[idx] = __float2bfloat16(hn - __bfloat162float(hh));
    if (hlast != nullptr && (idx >> 10) == SEQ - 1) hlast[idx & 1023] = hn;
    cudaTriggerProgrammaticLaunchCompletion();
}

__global__ __launch_bounds__(256)
void fc_kernel(const float* __restrict__ Hl, const float* __restrict__ Wfc,
               const float* __restrict__ bfc, float* __restrict__ out)
{
    __shared__ float hrow[HID];
    const int t = blockIdx.x;
    for (int k = threadIdx.x; k < HID; k += 256) hrow[k] = Hl[(size_t)t * HID + k];
    __syncthreads();
    for (int n = threadIdx.x; n < OUT_D; n += 256) {
        const float* w = Wfc + (size_t)n * HID;
        float s = 0.f;
#pragma unroll 8
        for (int k = 0; k < HID; k++) s = fmaf(hrow[k], w[k], s);
        out[(size_t)t * OUT_D + n] = s + bfc[n];
    }
}

// ---------------- launch ----------------
extern "C" void kernel_launch(void* const* d_in, const int* in_sizes, int n_in,
                              void* d_out, int out_size)
{
    const float* x     = (const float*)d_in[0];
    const float* w_ih1 = (const float*)d_in[1];
    const float* w_hh1 = (const float*)d_in[2];
    const float* b_ih1 = (const float*)d_in[3];
    const float* b_hh1 = (const float*)d_in[4];
    const float* w_ih2 = (const float*)d_in[5];
    const float* w_hh2 = (const float*)d_in[6];
    const float* b_ih2 = (const float*)d_in[7];
    const float* b_hh2 = (const float*)d_in[8];
    const float* w_fc  = (const float*)d_in[9];
    const float* b_fc  = (const float*)d_in[10];
    float* out = (float*)d_out;

    __nv_bfloat16 *xhi, *xlo, *wxh, *wxl, *whh, *whl, *hhi, *hlo;
    float *c, *gates, *hlast, *bias, *gx1;
    cudaGetSymbolAddress((void**)&xhi, g_xhi);
    cudaGetSymbolAddress((void**)&xlo, g_xlo);
    cudaGetSymbolAddress((void**)&wxh, g_wxh);
    cudaGetSymbolAddress((void**)&wxl, g_wxl);
    cudaGetSymbolAddress((void**)&whh, g_whh);
    cudaGetSymbolAddress((void**)&whl, g_whl);
    cudaGetSymbolAddress((void**)&hhi, g_hhi);
    cudaGetSymbolAddress((void**)&hlo, g_hlo);
    cudaGetSymbolAddress((void**)&c,     g_c);
    cudaGetSymbolAddress((void**)&gates, g_gates);
    cudaGetSymbolAddress((void**)&hlast, g_hlast);
    cudaGetSymbolAddress((void**)&bias,  g_bias);
    cudaGetSymbolAddress((void**)&gx1,   g_gx1);

    cudaFuncSetAttribute(gemm_x_all, cudaFuncAttributeMaxDynamicSharedMemorySize, SMEM_DYN);
    cudaFuncSetAttribute(gemm_h, cudaFuncAttributeMaxDynamicSharedMemorySize, SMEM_DYN);
    cudaFuncSetAttribute(gemm_xh, cudaFuncAttributeMaxDynamicSharedMemorySize, SMEM_DYN);

    const size_t nwx = (size_t)GATES_N * INPUT_D;
    const size_t nwh = (size_t)GATES_N * HID;

    // setup
    {
        const size_t nx = (size_t)STEPS * SEQ * INPUT_D;
        split_kernel<<<(unsigned)((nx + 255) / 256), 256>>>(x, xhi, xlo, nx, 255.0f);
        split_permute_w<<<(unsigned)((nwx + 255) / 256), 256>>>(w_ih1, wxh, wxl, 9);
        split_permute_w<<<(unsigned)((nwh + 255) / 256), 256>>>(w_hh1, whh, whl, 10);
        split_permute_w<<<(unsigned)((nwx + 255) / 256), 256>>>(w_ih2, wxh + nwx, wxl + nwx, 9);
        split_permute_w<<<(unsigned)((nwh + 255) / 256), 256>>>(w_hh2, whh + nwh, whl + nwh, 10);
        bias_combine<<<(GATES_N + 255) / 256, 256>>>(b_ih1, b_hh1, bias);
        bias_combine<<<(GATES_N + 255) / 256, 256>>>(b_ih2, b_hh2, bias + GATES_N);
    }
    zero_state_kernel<<<(SEQ * HID + 255) / 256, 256>>>();

    // precompute L1 x-gates: grid (32, 8, 128)
    {
        dim3 g(GATES_N / TILE_N, SEQ / TILE_M, STEPS);
        gemm_x_all<<<g, 256, SMEM_DYN>>>(xhi, xlo, wxh, wxl, bias, gx1);
    }

    // PDL launch configs
    cudaLaunchAttribute pdl_attr[1];
    pdl_attr[0].id = cudaLaunchAttributeProgrammaticStreamSerialization;
    pdl_attr[0].val.programmaticStreamSerializationAllowed = 1;

    cudaLaunchConfig_t gemm_cfg = {};
    gemm_cfg.gridDim = dim3(GATES_N / TILE_N, SEQ / TILE_M, 1);
    gemm_cfg.blockDim = dim3(256, 1, 1);
    gemm_cfg.dynamicSmemBytes = SMEM_DYN;
    gemm_cfg.stream = 0;
    gemm_cfg.attrs = pdl_attr;
    gemm_cfg.numAttrs = 1;

    cudaLaunchConfig_t cell_cfg = {};
    cell_cfg.gridDim = dim3((SEQ * HID) / 256, 1, 1);
    cell_cfg.blockDim = dim3(256, 1, 1);
    cell_cfg.dynamicSmemBytes = 0;
    cell_cfg.stream = 0;
    cell_cfg.attrs = pdl_attr;
    cell_cfg.numAttrs = 1;

    for (int t = 0; t < STEPS; ++t) {
        const __nv_bfloat16* xth = xhi + (size_t)t * SEQ * INPUT_D;
        const __nv_bfloat16* xtl = xlo + (size_t)t * SEQ * INPUT_D;
        float* hl = (float*)nullptr;

        // layer 1: h-GEMM + precomputed x-gates
        cudaLaunchKernelEx(&gemm_cfg, gemm_h,
                           (const __nv_bfloat16*)hhi, (const __nv_bfloat16*)hlo,
                           (const __nv_bfloat16*)whh, (const __nv_bfloat16*)whl,
                           (const float*)(gx1 + (size_t)t * SEQ * GATES_N), gates);
        cudaLaunchKernelEx(&cell_cfg, lstm_cell_kernel,
                           (const float*)gates, hhi, hlo, c, hl);

        // layer 2: full GEMM, x-first (overlaps cell1 via PDL)
        cudaLaunchKernelEx(&gemm_cfg, gemm_xh,
                           xth, xtl,
                           (const __nv_bfloat16*)hhi, (const __nv_bfloat16*)hlo,
                           (const __nv_bfloat16*)(wxh + nwx), (const __nv_bfloat16*)(wxl + nwx),
                           (const __nv_bfloat16*)(whh + nwh), (const __nv_bfloat16*)(whl + nwh),
                           (const float*)(bias + GATES_N), gates);
        float* hl2 = hlast + (size_t)t * HID;
        cudaLaunchKernelEx(&cell_cfg, lstm_cell_kernel,
                           (const float*)gates, hhi, hlo, c, hl2);
    }

    fc_kernel<<<STEPS, 256>>>(hlast, w_fc, b_fc, out);
}

// round 12
// speedup vs baseline: 1.0008x; 1.0008x over previous
#include <cuda_runtime.h>
#include <cuda_bf16.h>
#include <cstdint>
#include <math.h>

#define SEQ     1024
#define INPUT_D 512
#define HID     1024
#define GATES_N 4096
#define STEPS   128
#define OUT_D   1000

// ---------------- device scratch ----------------
__device__ __nv_bfloat16 g_xhi[(size_t)STEPS * SEQ * INPUT_D];
__device__ __nv_bfloat16 g_xlo[(size_t)STEPS * SEQ * INPUT_D];
__device__ __nv_bfloat16 g_wxh[2][GATES_N * INPUT_D];   // gate-interleaved rows
__device__ __nv_bfloat16 g_wxl[2][GATES_N * INPUT_D];
__device__ __nv_bfloat16 g_whh[2][GATES_N * HID];
__device__ __nv_bfloat16 g_whl[2][GATES_N * HID];
__device__ float g_bias[2][GATES_N];                     // permuted b_ih + b_hh
__device__ __nv_bfloat16 g_hhi[SEQ * HID];
__device__ __nv_bfloat16 g_hlo[SEQ * HID];
__device__ float g_c[SEQ * HID];
__device__ float g_gates[(size_t)SEQ * GATES_N];         // interleaved gates
__device__ float g_hlast[STEPS * HID];

// ---------------- helpers ----------------
__device__ __forceinline__ uint32_t smem_u32(const void* p) {
    return (uint32_t)__cvta_generic_to_shared(p);
}
__device__ __forceinline__ void cp16(uint32_t saddr, const void* gaddr) {
    asm volatile("cp.async.cg.shared.global [%0], [%1], 16;" :: "r"(saddr), "l"(gaddr) : "memory");
}
#define CP_COMMIT() asm volatile("cp.async.commit_group;" ::: "memory")
#define CP_WAIT(n)  asm volatile("cp.async.wait_group %0;" :: "n"(n) : "memory")

__device__ __forceinline__ uint32_t sw128(uint32_t off) {
    return off ^ ((off >> 3) & 0x70);
}

// ---------------- GEMM: K=32 superstages sharing A/B hi+lo sub-tiles ---------
#define TILE_M   128
#define TILE_N   128
#define SUP_K    32
#define NS       3
#define NRANGES  48          // 16 x-ranges (K=512) + 32 h-ranges (K=1024)
#define FIRST_H  16
#define AB_BYTES 16384       // A-comb (or B-comb): 128 rows x 128B (hi|lo)
#define STAGE_BYTES (2 * AB_BYTES)   // 32 KB
#define SMEM_DYN (NS * STAGE_BYTES)  // 96 KB -> 2 CTAs/SM

#define MMA4(ACC, BSRC) \
    asm volatile( \
        "mma.sync.aligned.m16n8k16.row.col.f32.bf16.bf16.f32 " \
        "{%0,%1,%2,%3}, {%4,%5,%6,%7}, {%8,%9}, {%0,%1,%2,%3};" \
        : "+f"(ACC[mt][nt][0]), "+f"(ACC[mt][nt][1]), \
          "+f"(ACC[mt][nt][2]), "+f"(ACC[mt][nt][3]) \
        : "r"(a0), "r"(a1), "r"(a2), "r"(a3), \
          "r"(BSRC[nt][0]), "r"(BSRC[nt][1]));

__global__ __launch_bounds__(256, 2)
void gemm_gates(const __nv_bfloat16* __restrict__ xhi, const __nv_bfloat16* __restrict__ xlo,
                const __nv_bfloat16* __restrict__ hhi, const __nv_bfloat16* __restrict__ hlo,
                const __nv_bfloat16* __restrict__ wxh, const __nv_bfloat16* __restrict__ wxl,
                const __nv_bfloat16* __restrict__ whh, const __nv_bfloat16* __restrict__ whl,
                const float* __restrict__ bsum,
                float* __restrict__ out)
{
    extern __shared__ __align__(1024) char smem_raw[];
    const uint32_t sbase = smem_u32(smem_raw);

    const int tid = threadIdx.x;
    const int wid = tid >> 5;
    const int lane = tid & 31;
    const int wm = wid & 1;          // 2 warps along M (64 rows)
    const int wn = wid >> 1;         // 4 warps along N (32 cols)
    const int bn = blockIdx.x * TILE_N;
    const int bm = blockIdx.y * TILE_M;

    // loader: per superstage each thread does 8 cp16 (2 per sub-tile)
    auto load_range = [&](int rr, int stage) {
        const bool isx = rr < FIRST_H;
        const int kst = isx ? INPUT_D : HID;
        const int k0 = (isx ? rr : rr - FIRST_H) * SUP_K;
        const __nv_bfloat16* pah = isx ? xhi : hhi;
        const __nv_bfloat16* pal = isx ? xlo : hlo;
        const __nv_bfloat16* pbh = isx ? wxh : whh;
        const __nv_bfloat16* pbl = isx ? wxl : whl;
        const uint32_t abase = sbase + stage * STAGE_BYTES;
        const uint32_t bbase = abase + AB_BYTES;
#pragma unroll
        for (int v = 0; v < 2; v++) {
            const int w = v * 256 + tid;          // 0..511
            const int row = w >> 2;               // 0..127
            const int c4 = (w & 3) * 16;          // byte offset within 64B half
            const int kk = k0 + c4 / 2;
            cp16(abase + sw128(row * 128 + c4),      pah + (size_t)(bm + row) * kst + kk);
            cp16(abase + sw128(row * 128 + 64 + c4), pal + (size_t)(bm + row) * kst + kk);
            cp16(bbase + sw128(row * 128 + c4),      pbh + (size_t)(bn + row) * kst + kk);
            cp16(bbase + sw128(row * 128 + 64 + c4), pbl + (size_t)(bn + row) * kst + kk);
        }
    };

    float acc[4][4][4];
#pragma unroll
    for (int i = 0; i < 4; i++)
#pragma unroll
        for (int j = 0; j < 4; j++)
#pragma unroll
            for (int q = 0; q < 4; q++) acc[i][j][q] = 0.0f;

    auto compute_stage = [&](int stage) {
        const uint32_t abase = sbase + stage * STAGE_BYTES;
        const uint32_t bbase = abase + AB_BYTES;
        const int g = lane >> 3, l7 = lane & 7;
        const int arow = wm * 64 + (lane & 15);
        const int acol = (lane >> 4) * 16;
#pragma unroll
        for (int ks = 0; ks < 2; ks++) {
            // B fragments: hi and lo halves (4 x4-ldsm)
            uint32_t bh[4][2], bl[4][2];
#pragma unroll
            for (int ntp = 0; ntp < 2; ntp++) {
                const int nrow = wn * 32 + ntp * 16 + ((g >> 1) << 3) + l7;
                const uint32_t ah = bbase + sw128(nrow * 128 + ks * 32 + (g & 1) * 16);
                asm volatile("ldmatrix.sync.aligned.m8n8.x4.shared.b16 {%0,%1,%2,%3}, [%4];"
                    : "=r"(bh[ntp * 2][0]), "=r"(bh[ntp * 2][1]),
                      "=r"(bh[ntp * 2 + 1][0]), "=r"(bh[ntp * 2 + 1][1])
                    : "r"(ah));
                const uint32_t al = bbase + sw128(nrow * 128 + 64 + ks * 32 + (g & 1) * 16);
                asm volatile("ldmatrix.sync.aligned.m8n8.x4.shared.b16 {%0,%1,%2,%3}, [%4];"
                    : "=r"(bl[ntp * 2][0]), "=r"(bl[ntp * 2][1]),
                      "=r"(bl[ntp * 2 + 1][0]), "=r"(bl[ntp * 2 + 1][1])
                    : "r"(al));
            }
            // products 0 (Ahi*Bhi) and 1 (Ahi*Blo): one A-ldsm serves both
#pragma unroll
            for (int mt = 0; mt < 4; mt++) {
                const int mrow = arow + mt * 16;
                const uint32_t aa = abase + sw128(mrow * 128 + ks * 32 + acol);
                uint32_t a0, a1, a2, a3;
                asm volatile("ldmatrix.sync.aligned.m8n8.x4.shared.b16 {%0,%1,%2,%3}, [%4];"
                    : "=r"(a0), "=r"(a1), "=r"(a2), "=r"(a3) : "r"(aa));
#pragma unroll
                for (int nt = 0; nt < 4; nt++) { MMA4(acc, bh) }
#pragma unroll
                for (int nt = 0; nt < 4; nt++) { MMA4(acc, bl) }
            }
            // product 2 (Alo*Bhi)
#pragma unroll
            for (int mt = 0; mt < 4; mt++) {
                const int mrow = arow + mt * 16;
                const uint32_t aa = abase + sw128(mrow * 128 + 64 + ks * 32 + acol);
                uint32_t a0, a1, a2, a3;
                asm volatile("ldmatrix.sync.aligned.m8n8.x4.shared.b16 {%0,%1,%2,%3}, [%4];"
                    : "=r"(a0), "=r"(a1), "=r"(a2), "=r"(a3) : "r"(aa));
#pragma unroll
                for (int nt = 0; nt < 4; nt++) { MMA4(acc, bh) }
            }
        }
    };

    // prologue: ranges 0..NS-2 are x-ranges (no dependency on upstream cell)
#pragma unroll
    for (int p = 0; p < NS - 1; p++) { load_range(p, p); CP_COMMIT(); }

#pragma unroll 1
    for (int i = 0; i < NRANGES; i++) {
        CP_WAIT(NS - 2);
        __syncthreads();
        const int nc = i + NS - 1;
        if (nc < NRANGES) {
            if (nc == FIRST_H)
                cudaGridDependencySynchronize();   // h final (upstream cell done)
            load_range(nc, nc % NS);
        }
        CP_COMMIT();
        compute_stage(i % NS);
    }

    // epilogue: add combined bias, write interleaved gates
#pragma unroll
    for (int mt = 0; mt < 4; mt++) {
        const int m0 = bm + wm * 64 + mt * 16 + (lane >> 2);
#pragma unroll
        for (int nt = 0; nt < 4; nt++) {
            const int n0 = bn + wn * 32 + nt * 8 + (lane & 3) * 2;
            const float bs0 = bsum[n0];
            const float bs1 = bsum[n0 + 1];
            float2 v0, v1;
            v0.x = acc[mt][nt][0] + bs0; v0.y = acc[mt][nt][1] + bs1;
            v1.x = acc[mt][nt][2] + bs0; v1.y = acc[mt][nt][3] + bs1;
            *reinterpret_cast<float2*>(out + (size_t)m0 * GATES_N + n0) = v0;
            *reinterpret_cast<float2*>(out + (size_t)(m0 + 8) * GATES_N + n0) = v1;
        }
    }
    cudaTriggerProgrammaticLaunchCompletion();
}

// ---------------- pointwise kernels ----------------
__global__ void split_kernel(const float* __restrict__ src, __nv_bfloat16* __restrict__ hi,
                             __nv_bfloat16* __restrict__ lo, size_t n, float scale)
{
    const size_t i = (size_t)blockIdx.x * blockDim.x + threadIdx.x;
    if (i < n) {
        const float v = src[i] * scale;
        const __nv_bfloat16 h = __float2bfloat16(v);
        hi[i] = h;
        lo[i] = __float2bfloat16(v - __bfloat162float(h));
    }
}

// permute rows to gate-interleaved order: new_row = 4*unit + gate
__global__ void split_permute_w(const float* __restrict__ src, __nv_bfloat16* __restrict__ hi,
                                __nv_bfloat16* __restrict__ lo, int kshift)
{
    const size_t i = (size_t)blockIdx.x * blockDim.x + threadIdx.x;
    const int K = 1 << kshift;
    if (i < (size_t)GATES_N << kshift) {
        const int row = (int)(i >> kshift);
        const int k = (int)(i & (K - 1));
        const int nrow = ((row & 1023) << 2) | (row >> 10);
        const float v = src[i];
        const __nv_bfloat16 h = __float2bfloat16(v);
        hi[(size_t)nrow * K + k] = h;
        lo[(size_t)nrow * K + k] = __float2bfloat16(v - __bfloat162float(h));
    }
}

__global__ void bias_combine(const float* __restrict__ b_ih, const float* __restrict__ b_hh,
                             float* __restrict__ bsum)
{
    const int i = blockIdx.x * blockDim.x + threadIdx.x;
    if (i < GATES_N) {
        const int ni = ((i & 1023) << 2) | (i >> 10);
        bsum[ni] = b_ih[i] + b_hh[i];
    }
}

__global__ void zero_state_kernel()
{
    const int i = blockIdx.x * blockDim.x + threadIdx.x;
    if (i < SEQ * HID) {
        g_hhi[i] = __float2bfloat16(0.f);
        g_hlo[i] = __float2bfloat16(0.f);
        g_c[i] = 0.f;
    }
}

__global__ __launch_bounds__(256)
void lstm_cell_kernel(const float* __restrict__ gates,   // interleaved [m][4u+g]
                      __nv_bfloat16* __restrict__ hhi, __nv_bfloat16* __restrict__ hlo,
                      float* __restrict__ c, float* __restrict__ hlast)
{
    cudaGridDependencySynchronize();
    const int idx = blockIdx.x * blockDim.x + threadIdx.x;   // m*1024 + u
    const float4 g4 = reinterpret_cast<const float4*>(gates)[idx];

    const float si = 1.0f / (1.0f + expf(-g4.x));
    const float sf = 1.0f / (1.0f + expf(-g4.y));
    const float tg = tanhf(g4.z);
    const float so = 1.0f / (1.0f + expf(-g4.w));

    const float cn = sf * c[idx] + si * tg;
    const float hn = so * tanhf(cn);
    c[idx] = cn;

    const __nv_bfloat16 hh = __float2bfloat16(hn);
    hhi[idx] = hh;
    hlo[idx] = __float2bfloat16(hn - __bfloat162float(hh));
    if (hlast != nullptr && (idx >> 10) == SEQ - 1) hlast[idx & 1023] = hn;
    cudaTriggerProgrammaticLaunchCompletion();
}

__global__ __launch_bounds__(256)
void fc_kernel(const float* __restrict__ Hl, const float* __restrict__ Wfc,
               const float* __restrict__ bfc, float* __restrict__ out)
{
    __shared__ float hrow[HID];
    const int t = blockIdx.x;
    for (int k = threadIdx.x; k < HID; k += 256) hrow[k] = Hl[(size_t)t * HID + k];
    __syncthreads();
    for (int n = threadIdx.x; n < OUT_D; n += 256) {
        const float* w = Wfc + (size_t)n * HID;
        float s = 0.f;
#pragma unroll 8
        for (int k = 0; k < HID; k++) s = fmaf(hrow[k], w[k], s);
        out[(size_t)t * OUT_D + n] = s + bfc[n];
    }
}

// ---------------- launch ----------------
extern "C" void kernel_launch(void* const* d_in, const int* in_sizes, int n_in,
                              void* d_out, int out_size)
{
    const float* x     = (const float*)d_in[0];
    const float* w_ih1 = (const float*)d_in[1];
    const float* w_hh1 = (const float*)d_in[2];
    const float* b_ih1 = (const float*)d_in[3];
    const float* b_hh1 = (const float*)d_in[4];
    const float* w_ih2 = (const float*)d_in[5];
    const float* w_hh2 = (const float*)d_in[6];
    const float* b_ih2 = (const float*)d_in[7];
    const float* b_hh2 = (const float*)d_in[8];
    const float* w_fc  = (const float*)d_in[9];
    const float* b_fc  = (const float*)d_in[10];
    float* out = (float*)d_out;

    __nv_bfloat16 *xhi, *xlo, *wxh, *wxl, *whh, *whl, *hhi, *hlo;
    float *c, *gates, *hlast, *bias;
    cudaGetSymbolAddress((void**)&xhi, g_xhi);
    cudaGetSymbolAddress((void**)&xlo, g_xlo);
    cudaGetSymbolAddress((void**)&wxh, g_wxh);
    cudaGetSymbolAddress((void**)&wxl, g_wxl);
    cudaGetSymbolAddress((void**)&whh, g_whh);
    cudaGetSymbolAddress((void**)&whl, g_whl);
    cudaGetSymbolAddress((void**)&hhi, g_hhi);
    cudaGetSymbolAddress((void**)&hlo, g_hlo);
    cudaGetSymbolAddress((void**)&c,     g_c);
    cudaGetSymbolAddress((void**)&gates, g_gates);
    cudaGetSymbolAddress((void**)&hlast, g_hlast);
    cudaGetSymbolAddress((void**)&bias,  g_bias);

    cudaFuncSetAttribute(gemm_gates, cudaFuncAttributeMaxDynamicSharedMemorySize, SMEM_DYN);

    const size_t nwx = (size_t)GATES_N * INPUT_D;
    const size_t nwh = (size_t)GATES_N * HID;

    // setup: split x (*255); permute+split weights; combine+permute biases
    {
        const size_t nx = (size_t)STEPS * SEQ * INPUT_D;
        split_kernel<<<(unsigned)((nx + 255) / 256), 256>>>(x, xhi, xlo, nx, 255.0f);
        split_permute_w<<<(unsigned)((nwx + 255) / 256), 256>>>(w_ih1, wxh, wxl, 9);
        split_permute_w<<<(unsigned)((nwh + 255) / 256), 256>>>(w_hh1, whh, whl, 10);
        split_permute_w<<<(unsigned)((nwx + 255) / 256), 256>>>(w_ih2, wxh + nwx, wxl + nwx, 9);
        split_permute_w<<<(unsigned)((nwh + 255) / 256), 256>>>(w_hh2, whh + nwh, whl + nwh, 10);
        bias_combine<<<(GATES_N + 255) / 256, 256>>>(b_ih1, b_hh1, bias);
        bias_combine<<<(GATES_N + 255) / 256, 256>>>(b_ih2, b_hh2, bias + GATES_N);
    }
    zero_state_kernel<<<(SEQ * HID + 255) / 256, 256>>>();

    // PDL launch configs
    cudaLaunchAttribute pdl_attr[1];
    pdl_attr[0].id = cudaLaunchAttributeProgrammaticStreamSerialization;
    pdl_attr[0].val.programmaticStreamSerializationAllowed = 1;

    cudaLaunchConfig_t gemm_cfg = {};
    gemm_cfg.gridDim = dim3(GATES_N / TILE_N, SEQ / TILE_M, 1);   // (32, 8)
    gemm_cfg.blockDim = dim3(256, 1, 1);
    gemm_cfg.dynamicSmemBytes = SMEM_DYN;
    gemm_cfg.stream = 0;
    gemm_cfg.attrs = pdl_attr;
    gemm_cfg.numAttrs = 1;

    cudaLaunchConfig_t cell_cfg = {};
    cell_cfg.gridDim = dim3((SEQ * HID) / 256, 1, 1);
    cell_cfg.blockDim = dim3(256, 1, 1);
    cell_cfg.dynamicSmemBytes = 0;
    cell_cfg.stream = 0;
    cell_cfg.attrs = pdl_attr;
    cell_cfg.numAttrs = 1;

    for (int t = 0; t < STEPS; ++t) {
        const __nv_bfloat16* xth = xhi + (size_t)t * SEQ * INPUT_D;
        const __nv_bfloat16* xtl = xlo + (size_t)t * SEQ * INPUT_D;
        float* hl = (float*)nullptr;

        cudaLaunchKernelEx(&gemm_cfg, gemm_gates,
                           xth, xtl,
                           (const __nv_bfloat16*)hhi, (const __nv_bfloat16*)hlo,
                           (const __nv_bfloat16*)wxh, (const __nv_bfloat16*)wxl,
                           (const __nv_bfloat16*)whh, (const __nv_bfloat16*)whl,
                           (const float*)bias, gates);
        cudaLaunchKernelEx(&cell_cfg, lstm_cell_kernel,
                           (const float*)gates, hhi, hlo, c, hl);

        cudaLaunchKernelEx(&gemm_cfg, gemm_gates,
                           xth, xtl,
                           (const __nv_bfloat16*)hhi, (const __nv_bfloat16*)hlo,
                           (const __nv_bfloat16*)(wxh + nwx), (const __nv_bfloat16*)(wxl + nwx),
                           (const __nv_bfloat16*)(whh + nwh), (const __nv_bfloat16*)(whl + nwh),
                           (const float*)(bias + GATES_N), gates);
        float* hl2 = hlast + (size_t)t * HID;
        cudaLaunchKernelEx(&cell_cfg, lstm_cell_kernel,
                           (const float*)gates, hhi, hlo, c, hl2);
    }

    fc_kernel<<<STEPS, 256>>>(hlast, w_fc, b_fc, out);
}

// round 13
// speedup vs baseline: 1.0040x; 1.0032x over previous
#include <cuda_runtime.h>
#include <cuda_bf16.h>
#include <cstdint>
#include <math.h>

#define SEQ     1024
#define INPUT_D 512
#define HID     1024
#define GATES_N 4096
#define STEPS   128
#define OUT_D   1000

// ---------------- device scratch ----------------
__device__ __nv_bfloat16 g_xhi[(size_t)STEPS * SEQ * INPUT_D];
__device__ __nv_bfloat16 g_xlo[(size_t)STEPS * SEQ * INPUT_D];
__device__ __nv_bfloat16 g_wxh[2][GATES_N * INPUT_D];   // gate-interleaved rows
__device__ __nv_bfloat16 g_wxl[2][GATES_N * INPUT_D];
__device__ __nv_bfloat16 g_whh[2][GATES_N * HID];
__device__ __nv_bfloat16 g_whl[2][GATES_N * HID];
__device__ float g_bias[2][GATES_N];                     // permuted b_ih + b_hh
__device__ __nv_bfloat16 g_hhi[SEQ * HID];
__device__ __nv_bfloat16 g_hlo[SEQ * HID];
__device__ float g_c[SEQ * HID];
__device__ float g_gates[(size_t)SEQ * GATES_N];         // interleaved gates
__device__ float g_hlast[STEPS * HID];

// ---------------- helpers ----------------
__device__ __forceinline__ uint32_t smem_u32(const void* p) {
    return (uint32_t)__cvta_generic_to_shared(p);
}
__device__ __forceinline__ void cp16(uint32_t saddr, const void* gaddr) {
    asm volatile("cp.async.cg.shared.global [%0], [%1], 16;" :: "r"(saddr), "l"(gaddr) : "memory");
}
#define CP_COMMIT() asm volatile("cp.async.commit_group;" ::: "memory")
#define CP_WAIT(n)  asm volatile("cp.async.wait_group %0;" :: "n"(n) : "memory")

__device__ __forceinline__ uint32_t sw128(uint32_t off) {
    return off ^ ((off >> 3) & 0x70);
}

// ---------------- GEMM: K=32 superstages sharing A/B hi+lo sub-tiles ---------
#define TILE_M   128
#define TILE_N   128
#define SUP_K    32
#define NS       3
#define NRANGES  48          // 16 x-ranges (K=512) + 32 h-ranges (K=1024)
#define FIRST_H  16
#define AB_BYTES 16384       // A-comb (or B-comb): 128 rows x 128B (hi|lo)
#define STAGE_BYTES (2 * AB_BYTES)   // 32 KB
#define SMEM_DYN (NS * STAGE_BYTES)  // 96 KB -> 2 CTAs/SM

#define MMA4(ACC, BSRC) \
    asm volatile( \
        "mma.sync.aligned.m16n8k16.row.col.f32.bf16.bf16.f32 " \
        "{%0,%1,%2,%3}, {%4,%5,%6,%7}, {%8,%9}, {%0,%1,%2,%3};" \
        : "+f"(ACC[mt][nt][0]), "+f"(ACC[mt][nt][1]), \
          "+f"(ACC[mt][nt][2]), "+f"(ACC[mt][nt][3]) \
        : "r"(a0), "r"(a1), "r"(a2), "r"(a3), \
          "r"(BSRC[nt][0]), "r"(BSRC[nt][1]));

__global__ __launch_bounds__(256, 2)
void gemm_gates(const __nv_bfloat16* __restrict__ xhi, const __nv_bfloat16* __restrict__ xlo,
                const __nv_bfloat16* __restrict__ hhi, const __nv_bfloat16* __restrict__ hlo,
                const __nv_bfloat16* __restrict__ wxh, const __nv_bfloat16* __restrict__ wxl,
                const __nv_bfloat16* __restrict__ whh, const __nv_bfloat16* __restrict__ whl,
                const float* __restrict__ bsum,
                float* __restrict__ out)
{
    extern __shared__ __align__(1024) char smem_raw[];
    const uint32_t sbase = smem_u32(smem_raw);

    const int tid = threadIdx.x;
    const int wid = tid >> 5;
    const int lane = tid & 31;
    const int wm = wid & 1;          // 2 warps along M (64 rows)
    const int wn = wid >> 1;         // 4 warps along N (32 cols)
    const int bn = blockIdx.x * TILE_N;
    const int bm = blockIdx.y * TILE_M;

    // loader: per superstage each thread does 8 cp16 (2 per sub-tile)
    auto load_range = [&](int rr, int stage) {
        const bool isx = rr < FIRST_H;
        const int kst = isx ? INPUT_D : HID;
        const int k0 = (isx ? rr : rr - FIRST_H) * SUP_K;
        const __nv_bfloat16* pah = isx ? xhi : hhi;
        const __nv_bfloat16* pal = isx ? xlo : hlo;
        const __nv_bfloat16* pbh = isx ? wxh : whh;
        const __nv_bfloat16* pbl = isx ? wxl : whl;
        const uint32_t abase = sbase + stage * STAGE_BYTES;
        const uint32_t bbase = abase + AB_BYTES;
#pragma unroll
        for (int v = 0; v < 2; v++) {
            const int w = v * 256 + tid;          // 0..511
            const int row = w >> 2;               // 0..127
            const int c4 = (w & 3) * 16;          // byte offset within 64B half
            const int kk = k0 + c4 / 2;
            cp16(abase + sw128(row * 128 + c4),      pah + (size_t)(bm + row) * kst + kk);
            cp16(abase + sw128(row * 128 + 64 + c4), pal + (size_t)(bm + row) * kst + kk);
            cp16(bbase + sw128(row * 128 + c4),      pbh + (size_t)(bn + row) * kst + kk);
            cp16(bbase + sw128(row * 128 + 64 + c4), pbl + (size_t)(bn + row) * kst + kk);
        }
    };

    float acc[4][4][4];
#pragma unroll
    for (int i = 0; i < 4; i++)
#pragma unroll
        for (int j = 0; j < 4; j++)
#pragma unroll
            for (int q = 0; q < 4; q++) acc[i][j][q] = 0.0f;

    auto compute_stage = [&](int stage) {
        const uint32_t abase = sbase + stage * STAGE_BYTES;
        const uint32_t bbase = abase + AB_BYTES;
        const int g = lane >> 3, l7 = lane & 7;
        const int arow = wm * 64 + (lane & 15);
        const int acol = (lane >> 4) * 16;
#pragma unroll
        for (int ks = 0; ks < 2; ks++) {
            uint32_t bh[4][2], bl[4][2];
#pragma unroll
            for (int ntp = 0; ntp < 2; ntp++) {
                const int nrow = wn * 32 + ntp * 16 + ((g >> 1) << 3) + l7;
                const uint32_t ah = bbase + sw128(nrow * 128 + ks * 32 + (g & 1) * 16);
                asm volatile("ldmatrix.sync.aligned.m8n8.x4.shared.b16 {%0,%1,%2,%3}, [%4];"
                    : "=r"(bh[ntp * 2][0]), "=r"(bh[ntp * 2][1]),
                      "=r"(bh[ntp * 2 + 1][0]), "=r"(bh[ntp * 2 + 1][1])
                    : "r"(ah));
                const uint32_t al = bbase + sw128(nrow * 128 + 64 + ks * 32 + (g & 1) * 16);
                asm volatile("ldmatrix.sync.aligned.m8n8.x4.shared.b16 {%0,%1,%2,%3}, [%4];"
                    : "=r"(bl[ntp * 2][0]), "=r"(bl[ntp * 2][1]),
                      "=r"(bl[ntp * 2 + 1][0]), "=r"(bl[ntp * 2 + 1][1])
                    : "r"(al));
            }
            // products 0 (Ahi*Bhi) and 1 (Ahi*Blo): one A-ldsm serves both
#pragma unroll
            for (int mt = 0; mt < 4; mt++) {
                const int mrow = arow + mt * 16;
                const uint32_t aa = abase + sw128(mrow * 128 + ks * 32 + acol);
                uint32_t a0, a1, a2, a3;
                asm volatile("ldmatrix.sync.aligned.m8n8.x4.shared.b16 {%0,%1,%2,%3}, [%4];"
                    : "=r"(a0), "=r"(a1), "=r"(a2), "=r"(a3) : "r"(aa));
#pragma unroll
                for (int nt = 0; nt < 4; nt++) { MMA4(acc, bh) }
#pragma unroll
                for (int nt = 0; nt < 4; nt++) { MMA4(acc, bl) }
            }
            // product 2 (Alo*Bhi)
#pragma unroll
            for (int mt = 0; mt < 4; mt++) {
                const int mrow = arow + mt * 16;
                const uint32_t aa = abase + sw128(mrow * 128 + 64 + ks * 32 + acol);
                uint32_t a0, a1, a2, a3;
                asm volatile("ldmatrix.sync.aligned.m8n8.x4.shared.b16 {%0,%1,%2,%3}, [%4];"
                    : "=r"(a0), "=r"(a1), "=r"(a2), "=r"(a3) : "r"(aa));
#pragma unroll
                for (int nt = 0; nt < 4; nt++) { MMA4(acc, bh) }
            }
        }
    };

    // prologue: ranges 0..NS-2 are x-ranges (no dependency on upstream cell)
#pragma unroll
    for (int p = 0; p < NS - 1; p++) { load_range(p, p); CP_COMMIT(); }

#pragma unroll 1
    for (int i = 0; i < NRANGES; i++) {
        CP_WAIT(NS - 2);
        __syncthreads();
        const int nc = i + NS - 1;
        if (nc < NRANGES) {
            if (nc == FIRST_H)
                cudaGridDependencySynchronize();   // h final (upstream cell done)
            load_range(nc, nc % NS);
        }
        CP_COMMIT();
        compute_stage(i % NS);
    }

    // allow downstream cell blocks to take slots while we run the epilogue
    cudaTriggerProgrammaticLaunchCompletion();

    // epilogue: add combined bias, write interleaved gates
#pragma unroll
    for (int mt = 0; mt < 4; mt++) {
        const int m0 = bm + wm * 64 + mt * 16 + (lane >> 2);
#pragma unroll
        for (int nt = 0; nt < 4; nt++) {
            const int n0 = bn + wn * 32 + nt * 8 + (lane & 3) * 2;
            const float bs0 = bsum[n0];
            const float bs1 = bsum[n0 + 1];
            float2 v0, v1;
            v0.x = acc[mt][nt][0] + bs0; v0.y = acc[mt][nt][1] + bs1;
            v1.x = acc[mt][nt][2] + bs0; v1.y = acc[mt][nt][3] + bs1;
            *reinterpret_cast<float2*>(out + (size_t)m0 * GATES_N + n0) = v0;
            *reinterpret_cast<float2*>(out + (size_t)(m0 + 8) * GATES_N + n0) = v1;
        }
    }
}

// ---------------- pointwise kernels ----------------
__global__ void split_kernel(const float* __restrict__ src, __nv_bfloat16* __restrict__ hi,
                             __nv_bfloat16* __restrict__ lo, size_t n, float scale)
{
    const size_t i = (size_t)blockIdx.x * blockDim.x + threadIdx.x;
    if (i < n) {
        const float v = src[i] * scale;
        const __nv_bfloat16 h = __float2bfloat16(v);
        hi[i] = h;
        lo[i] = __float2bfloat16(v - __bfloat162float(h));
    }
}

// permute rows to gate-interleaved order: new_row = 4*unit + gate
__global__ void split_permute_w(const float* __restrict__ src, __nv_bfloat16* __restrict__ hi,
                                __nv_bfloat16* __restrict__ lo, int kshift)
{
    const size_t i = (size_t)blockIdx.x * blockDim.x + threadIdx.x;
    const int K = 1 << kshift;
    if (i < (size_t)GATES_N << kshift) {
        const int row = (int)(i >> kshift);
        const int k = (int)(i & (K - 1));
        const int nrow = ((row & 1023) << 2) | (row >> 10);
        const float v = src[i];
        const __nv_bfloat16 h = __float2bfloat16(v);
        hi[(size_t)nrow * K + k] = h;
        lo[(size_t)nrow * K + k] = __float2bfloat16(v - __bfloat162float(h));
    }
}

__global__ void bias_combine(const float* __restrict__ b_ih, const float* __restrict__ b_hh,
                             float* __restrict__ bsum)
{
    const int i = blockIdx.x * blockDim.x + threadIdx.x;
    if (i < GATES_N) {
        const int ni = ((i & 1023) << 2) | (i >> 10);
        bsum[ni] = b_ih[i] + b_hh[i];
    }
}

__global__ void zero_state_kernel()
{
    const int i = blockIdx.x * blockDim.x + threadIdx.x;
    if (i < SEQ * HID) {
        g_hhi[i] = __float2bfloat16(0.f);
        g_hlo[i] = __float2bfloat16(0.f);
        g_c[i] = 0.f;
    }
}

__global__ __launch_bounds__(256)
void lstm_cell_kernel(const float* __restrict__ gates,   // interleaved [m][4u+g]
                      __nv_bfloat16* __restrict__ hhi, __nv_bfloat16* __restrict__ hlo,
                      float* __restrict__ c, float* __restrict__ hlast)
{
    // trigger FIRST: the next GEMM may launch now and run its x-ranges on idle
    // SMs while the current GEMM tail + this cell execute. Data safety comes
    // from gridDepSync (always waits for full upstream completion).
    cudaTriggerProgrammaticLaunchCompletion();
    cudaGridDependencySynchronize();

    const int idx = blockIdx.x * blockDim.x + threadIdx.x;   // m*1024 + u
    const float4 g4 = reinterpret_cast<const float4*>(gates)[idx];

    const float si = 1.0f / (1.0f + expf(-g4.x));
    const float sf = 1.0f / (1.0f + expf(-g4.y));
    const float tg = tanhf(g4.z);
    const float so = 1.0f / (1.0f + expf(-g4.w));

    const float cn = sf * c[idx] + si * tg;
    const float hn = so * tanhf(cn);
    c[idx] = cn;

    const __nv_bfloat16 hh = __float2bfloat16(hn);
    hhi[idx] = hh;
    hlo[idx] = __float2bfloat16(hn - __bfloat162float(hh));
    if (hlast != nullptr && (idx >> 10) == SEQ - 1) hlast[idx & 1023] = hn;
}

__global__ __launch_bounds__(256)
void fc_kernel(const float* __restrict__ Hl, const float* __restrict__ Wfc,
               const float* __restrict__ bfc, float* __restrict__ out)
{
    __shared__ float hrow[HID];
    const int t = blockIdx.x;
    for (int k = threadIdx.x; k < HID; k += 256) hrow[k] = Hl[(size_t)t * HID + k];
    __syncthreads();
    for (int n = threadIdx.x; n < OUT_D; n += 256) {
        const float* w = Wfc + (size_t)n * HID;
        float s = 0.f;
#pragma unroll 8
        for (int k = 0; k < HID; k++) s = fmaf(hrow[k], w[k], s);
        out[(size_t)t * OUT_D + n] = s + bfc[n];
    }
}

// ---------------- launch ----------------
extern "C" void kernel_launch(void* const* d_in, const int* in_sizes, int n_in,
                              void* d_out, int out_size)
{
    const float* x     = (const float*)d_in[0];
    const float* w_ih1 = (const float*)d_in[1];
    const float* w_hh1 = (const float*)d_in[2];
    const float* b_ih1 = (const float*)d_in[3];
    const float* b_hh1 = (const float*)d_in[4];
    const float* w_ih2 = (const float*)d_in[5];
    const float* w_hh2 = (const float*)d_in[6];
    const float* b_ih2 = (const float*)d_in[7];
    const float* b_hh2 = (const float*)d_in[8];
    const float* w_fc  = (const float*)d_in[9];
    const float* b_fc  = (const float*)d_in[10];
    float* out = (float*)d_out;

    __nv_bfloat16 *xhi, *xlo, *wxh, *wxl, *whh, *whl, *hhi, *hlo;
    float *c, *gates, *hlast, *bias;
    cudaGetSymbolAddress((void**)&xhi, g_xhi);
    cudaGetSymbolAddress((void**)&xlo, g_xlo);
    cudaGetSymbolAddress((void**)&wxh, g_wxh);
    cudaGetSymbolAddress((void**)&wxl, g_wxl);
    cudaGetSymbolAddress((void**)&whh, g_whh);
    cudaGetSymbolAddress((void**)&whl, g_whl);
    cudaGetSymbolAddress((void**)&hhi, g_hhi);
    cudaGetSymbolAddress((void**)&hlo, g_hlo);
    cudaGetSymbolAddress((void**)&c,     g_c);
    cudaGetSymbolAddress((void**)&gates, g_gates);
    cudaGetSymbolAddress((void**)&hlast, g_hlast);
    cudaGetSymbolAddress((void**)&bias,  g_bias);

    cudaFuncSetAttribute(gemm_gates, cudaFuncAttributeMaxDynamicSharedMemorySize, SMEM_DYN);

    const size_t nwx = (size_t)GATES_N * INPUT_D;
    const size_t nwh = (size_t)GATES_N * HID;

    // setup: split x (*255); permute+split weights; combine+permute biases
    {
        const size_t nx = (size_t)STEPS * SEQ * INPUT_D;
        split_kernel<<<(unsigned)((nx + 255) / 256), 256>>>(x, xhi, xlo, nx, 255.0f);
        split_permute_w<<<(unsigned)((nwx + 255) / 256), 256>>>(w_ih1, wxh, wxl, 9);
        split_permute_w<<<(unsigned)((nwh + 255) / 256), 256>>>(w_hh1, whh, whl, 10);
        split_permute_w<<<(unsigned)((nwx + 255) / 256), 256>>>(w_ih2, wxh + nwx, wxl + nwx, 9);
        split_permute_w<<<(unsigned)((nwh + 255) / 256), 256>>>(w_hh2, whh + nwh, whl + nwh, 10);
        bias_combine<<<(GATES_N + 255) / 256, 256>>>(b_ih1, b_hh1, bias);
        bias_combine<<<(GATES_N + 255) / 256, 256>>>(b_ih2, b_hh2, bias + GATES_N);
    }
    zero_state_kernel<<<(SEQ * HID + 255) / 256, 256>>>();

    // PDL launch configs
    cudaLaunchAttribute pdl_attr[1];
    pdl_attr[0].id = cudaLaunchAttributeProgrammaticStreamSerialization;
    pdl_attr[0].val.programmaticStreamSerializationAllowed = 1;

    cudaLaunchConfig_t gemm_cfg = {};
    gemm_cfg.gridDim = dim3(GATES_N / TILE_N, SEQ / TILE_M, 1);   // (32, 8)
    gemm_cfg.blockDim = dim3(256, 1, 1);
    gemm_cfg.dynamicSmemBytes = SMEM_DYN;
    gemm_cfg.stream = 0;
    gemm_cfg.attrs = pdl_attr;
    gemm_cfg.numAttrs = 1;

    cudaLaunchConfig_t cell_cfg = {};
    cell_cfg.gridDim = dim3((SEQ * HID) / 256, 1, 1);
    cell_cfg.blockDim = dim3(256, 1, 1);
    cell_cfg.dynamicSmemBytes = 0;
    cell_cfg.stream = 0;
    cell_cfg.attrs = pdl_attr;
    cell_cfg.numAttrs = 1;

    for (int t = 0; t < STEPS; ++t) {
        const __nv_bfloat16* xth = xhi + (size_t)t * SEQ * INPUT_D;
        const __nv_bfloat16* xtl = xlo + (size_t)t * SEQ * INPUT_D;
        float* hl = (float*)nullptr;

        cudaLaunchKernelEx(&gemm_cfg, gemm_gates,
                           xth, xtl,
                           (const __nv_bfloat16*)hhi, (const __nv_bfloat16*)hlo,
                           (const __nv_bfloat16*)wxh, (const __nv_bfloat16*)wxl,
                           (const __nv_bfloat16*)whh, (const __nv_bfloat16*)whl,
                           (const float*)bias, gates);
        cudaLaunchKernelEx(&cell_cfg, lstm_cell_kernel,
                           (const float*)gates, hhi, hlo, c, hl);

        cudaLaunchKernelEx(&gemm_cfg, gemm_gates,
                           xth, xtl,
                           (const __nv_bfloat16*)hhi, (const __nv_bfloat16*)hlo,
                           (const __nv_bfloat16*)(wxh + nwx), (const __nv_bfloat16*)(wxl + nwx),
                           (const __nv_bfloat16*)(whh + nwh), (const __nv_bfloat16*)(whl + nwh),
                           (const float*)(bias + GATES_N), gates);
        float* hl2 = hlast + (size_t)t * HID;
        cudaLaunchKernelEx(&cell_cfg, lstm_cell_kernel,
                           (const float*)gates, hhi, hlo, c, hl2);
    }

    fc_kernel<<<STEPS, 256>>>(hlast, w_fc, b_fc, out);
}

// round 14
// speedup vs baseline: 1.0973x; 1.0930x over previous
#include <cuda_runtime.h>
#include <cuda_bf16.h>
#include <cstdint>
#include <math.h>

#define SEQ     1024
#define INPUT_D 512
#define HID     1024
#define GATES_N 4096
#define STEPS   128
#define OUT_D   1000

// ---------------- device scratch ----------------
__device__ __nv_bfloat16 g_xhi[(size_t)STEPS * SEQ * INPUT_D];
__device__ __nv_bfloat16 g_xlo[(size_t)STEPS * SEQ * INPUT_D];
__device__ __nv_bfloat16 g_wxh[2][GATES_N * INPUT_D];   // gate-interleaved rows
__device__ __nv_bfloat16 g_wxl[2][GATES_N * INPUT_D];
__device__ __nv_bfloat16 g_whh[2][GATES_N * HID];
__device__ __nv_bfloat16 g_whl[2][GATES_N * HID];
__device__ float g_bias[2][GATES_N];                     // permuted b_ih + b_hh
__device__ __nv_bfloat16 g_hhi[SEQ * HID];
__device__ __nv_bfloat16 g_hlo[SEQ * HID];
__device__ float g_c[SEQ * HID];
__device__ float g_gates[(size_t)SEQ * GATES_N];         // interleaved gates
__device__ float g_hlast[STEPS * HID];

// ---------------- helpers ----------------
__device__ __forceinline__ uint32_t smem_u32(const void* p) {
    return (uint32_t)__cvta_generic_to_shared(p);
}
__device__ __forceinline__ void cp16(uint32_t saddr, const void* gaddr) {
    asm volatile("cp.async.cg.shared.global [%0], [%1], 16;" :: "r"(saddr), "l"(gaddr) : "memory");
}
#define CP_COMMIT() asm volatile("cp.async.commit_group;" ::: "memory")
#define CP_WAIT(n)  asm volatile("cp.async.wait_group %0;" :: "n"(n) : "memory")

__device__ __forceinline__ uint32_t sw128(uint32_t off) {
    return off ^ ((off >> 3) & 0x70);
}

// ---------------- GEMM: 64x64 tiles (1024 jobs -> balanced waves) ------------
#define TILE_M   64
#define TILE_N   64
#define SUP_K    32
#define NS       3
#define NRANGES  48          // 16 x-ranges (K=512) + 32 h-ranges (K=1024)
#define FIRST_H  16
#define AB_BYTES 8192        // A-comb (or B-comb): 64 rows x 128B (hi|lo)
#define STAGE_BYTES (2 * AB_BYTES)   // 16 KB
#define SMEM_DYN (NS * STAGE_BYTES)  // 48 KB -> 4 CTAs/SM

#define MMA4(ACC, BSRC) \
    asm volatile( \
        "mma.sync.aligned.m16n8k16.row.col.f32.bf16.bf16.f32 " \
        "{%0,%1,%2,%3}, {%4,%5,%6,%7}, {%8,%9}, {%0,%1,%2,%3};" \
        : "+f"(ACC[mt][nt][0]), "+f"(ACC[mt][nt][1]), \
          "+f"(ACC[mt][nt][2]), "+f"(ACC[mt][nt][3]) \
        : "r"(a0), "r"(a1), "r"(a2), "r"(a3), \
          "r"(BSRC[nt][0]), "r"(BSRC[nt][1]));

__global__ __launch_bounds__(128, 4)
void gemm_gates(const __nv_bfloat16* __restrict__ xhi, const __nv_bfloat16* __restrict__ xlo,
                const __nv_bfloat16* __restrict__ hhi, const __nv_bfloat16* __restrict__ hlo,
                const __nv_bfloat16* __restrict__ wxh, const __nv_bfloat16* __restrict__ wxl,
                const __nv_bfloat16* __restrict__ whh, const __nv_bfloat16* __restrict__ whl,
                const float* __restrict__ bsum,
                float* __restrict__ out)
{
    extern __shared__ __align__(1024) char smem_raw[];
    const uint32_t sbase = smem_u32(smem_raw);

    const int tid = threadIdx.x;
    const int wid = tid >> 5;
    const int lane = tid & 31;
    const int wm = wid & 1;          // 2 warps along M (32 rows)
    const int wn = wid >> 1;         // 2 warps along N (32 cols)
    const int bn = blockIdx.x * TILE_N;
    const int bm = blockIdx.y * TILE_M;

    // loader: per superstage each thread does 8 cp16 (2 per sub-tile)
    auto load_range = [&](int rr, int stage) {
        const bool isx = rr < FIRST_H;
        const int kst = isx ? INPUT_D : HID;
        const int k0 = (isx ? rr : rr - FIRST_H) * SUP_K;
        const __nv_bfloat16* pah = isx ? xhi : hhi;
        const __nv_bfloat16* pal = isx ? xlo : hlo;
        const __nv_bfloat16* pbh = isx ? wxh : whh;
        const __nv_bfloat16* pbl = isx ? wxl : whl;
        const uint32_t abase = sbase + stage * STAGE_BYTES;
        const uint32_t bbase = abase + AB_BYTES;
#pragma unroll
        for (int v = 0; v < 2; v++) {
            const int w = v * 128 + tid;          // 0..255
            const int row = w >> 2;               // 0..63
            const int c4 = (w & 3) * 16;          // 16B block within 64B half
            const int kk = k0 + c4 / 2;
            cp16(abase + sw128(row * 128 + c4),      pah + (size_t)(bm + row) * kst + kk);
            cp16(abase + sw128(row * 128 + 64 + c4), pal + (size_t)(bm + row) * kst + kk);
            cp16(bbase + sw128(row * 128 + c4),      pbh + (size_t)(bn + row) * kst + kk);
            cp16(bbase + sw128(row * 128 + 64 + c4), pbl + (size_t)(bn + row) * kst + kk);
        }
    };

    float acc[2][4][4];
#pragma unroll
    for (int i = 0; i < 2; i++)
#pragma unroll
        for (int j = 0; j < 4; j++)
#pragma unroll
            for (int q = 0; q < 4; q++) acc[i][j][q] = 0.0f;

    auto compute_stage = [&](int stage) {
        const uint32_t abase = sbase + stage * STAGE_BYTES;
        const uint32_t bbase = abase + AB_BYTES;
        const int g = lane >> 3, l7 = lane & 7;
        const int arow = wm * 32 + (lane & 15);
        const int acol = (lane >> 4) * 16;
#pragma unroll
        for (int ks = 0; ks < 2; ks++) {
            // B fragments: hi and lo halves (32 cols -> 2 x4-ldsm each)
            uint32_t bh[4][2], bl[4][2];
#pragma unroll
            for (int ntp = 0; ntp < 2; ntp++) {
                const int nrow = wn * 32 + ntp * 16 + ((g >> 1) << 3) + l7;
                const uint32_t ah = bbase + sw128(nrow * 128 + ks * 32 + (g & 1) * 16);
                asm volatile("ldmatrix.sync.aligned.m8n8.x4.shared.b16 {%0,%1,%2,%3}, [%4];"
                    : "=r"(bh[ntp * 2][0]), "=r"(bh[ntp * 2][1]),
                      "=r"(bh[ntp * 2 + 1][0]), "=r"(bh[ntp * 2 + 1][1])
                    : "r"(ah));
                const uint32_t al = bbase + sw128(nrow * 128 + 64 + ks * 32 + (g & 1) * 16);
                asm volatile("ldmatrix.sync.aligned.m8n8.x4.shared.b16 {%0,%1,%2,%3}, [%4];"
                    : "=r"(bl[ntp * 2][0]), "=r"(bl[ntp * 2][1]),
                      "=r"(bl[ntp * 2 + 1][0]), "=r"(bl[ntp * 2 + 1][1])
                    : "r"(al));
            }
            // products 0 (Ahi*Bhi) and 1 (Ahi*Blo): one A-ldsm serves both
#pragma unroll
            for (int mt = 0; mt < 2; mt++) {
                const int mrow = arow + mt * 16;
                const uint32_t aa = abase + sw128(mrow * 128 + ks * 32 + acol);
                uint32_t a0, a1, a2, a3;
                asm volatile("ldmatrix.sync.aligned.m8n8.x4.shared.b16 {%0,%1,%2,%3}, [%4];"
                    : "=r"(a0), "=r"(a1), "=r"(a2), "=r"(a3) : "r"(aa));
#pragma unroll
                for (int nt = 0; nt < 4; nt++) { MMA4(acc, bh) }
#pragma unroll
                for (int nt = 0; nt < 4; nt++) { MMA4(acc, bl) }
            }
            // product 2 (Alo*Bhi)
#pragma unroll
            for (int mt = 0; mt < 2; mt++) {
                const int mrow = arow + mt * 16;
                const uint32_t aa = abase + sw128(mrow * 128 + 64 + ks * 32 + acol);
                uint32_t a0, a1, a2, a3;
                asm volatile("ldmatrix.sync.aligned.m8n8.x4.shared.b16 {%0,%1,%2,%3}, [%4];"
                    : "=r"(a0), "=r"(a1), "=r"(a2), "=r"(a3) : "r"(aa));
#pragma unroll
                for (int nt = 0; nt < 4; nt++) { MMA4(acc, bh) }
            }
        }
    };

    // prologue: ranges 0..NS-2 are x-ranges (no dependency on upstream cell)
#pragma unroll
    for (int p = 0; p < NS - 1; p++) { load_range(p, p); CP_COMMIT(); }

#pragma unroll 1
    for (int i = 0; i < NRANGES; i++) {
        CP_WAIT(NS - 2);
        __syncthreads();
        const int nc = i + NS - 1;
        if (nc < NRANGES) {
            if (nc == FIRST_H)
                cudaGridDependencySynchronize();   // h final (upstream cell done)
            load_range(nc, nc % NS);
        }
        CP_COMMIT();
        compute_stage(i % NS);
    }

    // allow downstream blocks to take slots during the epilogue
    cudaTriggerProgrammaticLaunchCompletion();

    // epilogue: add combined bias, write interleaved gates
#pragma unroll
    for (int mt = 0; mt < 2; mt++) {
        const int m0 = bm + wm * 32 + mt * 16 + (lane >> 2);
#pragma unroll
        for (int nt = 0; nt < 4; nt++) {
            const int n0 = bn + wn * 32 + nt * 8 + (lane & 3) * 2;
            const float bs0 = bsum[n0];
            const float bs1 = bsum[n0 + 1];
            float2 v0, v1;
            v0.x = acc[mt][nt][0] + bs0; v0.y = acc[mt][nt][1] + bs1;
            v1.x = acc[mt][nt][2] + bs0; v1.y = acc[mt][nt][3] + bs1;
            *reinterpret_cast<float2*>(out + (size_t)m0 * GATES_N + n0) = v0;
            *reinterpret_cast<float2*>(out + (size_t)(m0 + 8) * GATES_N + n0) = v1;
        }
    }
}

// ---------------- pointwise kernels ----------------
__global__ void split_kernel(const float* __restrict__ src, __nv_bfloat16* __restrict__ hi,
                             __nv_bfloat16* __restrict__ lo, size_t n, float scale)
{
    const size_t i = (size_t)blockIdx.x * blockDim.x + threadIdx.x;
    if (i < n) {
        const float v = src[i] * scale;
        const __nv_bfloat16 h = __float2bfloat16(v);
        hi[i] = h;
        lo[i] = __float2bfloat16(v - __bfloat162float(h));
    }
}

// permute rows to gate-interleaved order: new_row = 4*unit + gate
__global__ void split_permute_w(const float* __restrict__ src, __nv_bfloat16* __restrict__ hi,
                                __nv_bfloat16* __restrict__ lo, int kshift)
{
    const size_t i = (size_t)blockIdx.x * blockDim.x + threadIdx.x;
    const int K = 1 << kshift;
    if (i < (size_t)GATES_N << kshift) {
        const int row = (int)(i >> kshift);
        const int k = (int)(i & (K - 1));
        const int nrow = ((row & 1023) << 2) | (row >> 10);
        const float v = src[i];
        const __nv_bfloat16 h = __float2bfloat16(v);
        hi[(size_t)nrow * K + k] = h;
        lo[(size_t)nrow * K + k] = __float2bfloat16(v - __bfloat162float(h));
    }
}

__global__ void bias_combine(const float* __restrict__ b_ih, const float* __restrict__ b_hh,
                             float* __restrict__ bsum)
{
    const int i = blockIdx.x * blockDim.x + threadIdx.x;
    if (i < GATES_N) {
        const int ni = ((i & 1023) << 2) | (i >> 10);
        bsum[ni] = b_ih[i] + b_hh[i];
    }
}

__global__ void zero_state_kernel()
{
    const int i = blockIdx.x * blockDim.x + threadIdx.x;
    if (i < SEQ * HID) {
        g_hhi[i] = __float2bfloat16(0.f);
        g_hlo[i] = __float2bfloat16(0.f);
        g_c[i] = 0.f;
    }
}

__global__ __launch_bounds__(256)
void lstm_cell_kernel(const float* __restrict__ gates,   // interleaved [m][4u+g]
                      __nv_bfloat16* __restrict__ hhi, __nv_bfloat16* __restrict__ hlo,
                      float* __restrict__ c, float* __restrict__ hlast)
{
    cudaTriggerProgrammaticLaunchCompletion();
    cudaGridDependencySynchronize();

    const int idx = blockIdx.x * blockDim.x + threadIdx.x;   // m*1024 + u
    const float4 g4 = reinterpret_cast<const float4*>(gates)[idx];

    const float si = 1.0f / (1.0f + expf(-g4.x));
    const float sf = 1.0f / (1.0f + expf(-g4.y));
    const float tg = tanhf(g4.z);
    const float so = 1.0f / (1.0f + expf(-g4.w));

    const float cn = sf * c[idx] + si * tg;
    const float hn = so * tanhf(cn);
    c[idx] = cn;

    const __nv_bfloat16 hh = __float2bfloat16(hn);
    hhi[idx] = hh;
    hlo[idx] = __float2bfloat16(hn - __bfloat162float(hh));
    if (hlast != nullptr && (idx >> 10) == SEQ - 1) hlast[idx & 1023] = hn;
}

__global__ __launch_bounds__(256)
void fc_kernel(const float* __restrict__ Hl, const float* __restrict__ Wfc,
               const float* __restrict__ bfc, float* __restrict__ out)
{
    __shared__ float hrow[HID];
    const int t = blockIdx.x;
    for (int k = threadIdx.x; k < HID; k += 256) hrow[k] = Hl[(size_t)t * HID + k];
    __syncthreads();
    for (int n = threadIdx.x; n < OUT_D; n += 256) {
        const float* w = Wfc + (size_t)n * HID;
        float s = 0.f;
#pragma unroll 8
        for (int k = 0; k < HID; k++) s = fmaf(hrow[k], w[k], s);
        out[(size_t)t * OUT_D + n] = s + bfc[n];
    }
}

// ---------------- launch ----------------
extern "C" void kernel_launch(void* const* d_in, const int* in_sizes, int n_in,
                              void* d_out, int out_size)
{
    const float* x     = (const float*)d_in[0];
    const float* w_ih1 = (const float*)d_in[1];
    const float* w_hh1 = (const float*)d_in[2];
    const float* b_ih1 = (const float*)d_in[3];
    const float* b_hh1 = (const float*)d_in[4];
    const float* w_ih2 = (const float*)d_in[5];
    const float* w_hh2 = (const float*)d_in[6];
    const float* b_ih2 = (const float*)d_in[7];
    const float* b_hh2 = (const float*)d_in[8];
    const float* w_fc  = (const float*)d_in[9];
    const float* b_fc  = (const float*)d_in[10];
    float* out = (float*)d_out;

    __nv_bfloat16 *xhi, *xlo, *wxh, *wxl, *whh, *whl, *hhi, *hlo;
    float *c, *gates, *hlast, *bias;
    cudaGetSymbolAddress((void**)&xhi, g_xhi);
    cudaGetSymbolAddress((void**)&xlo, g_xlo);
    cudaGetSymbolAddress((void**)&wxh, g_wxh);
    cudaGetSymbolAddress((void**)&wxl, g_wxl);
    cudaGetSymbolAddress((void**)&whh, g_whh);
    cudaGetSymbolAddress((void**)&whl, g_whl);
    cudaGetSymbolAddress((void**)&hhi, g_hhi);
    cudaGetSymbolAddress((void**)&hlo, g_hlo);
    cudaGetSymbolAddress((void**)&c,     g_c);
    cudaGetSymbolAddress((void**)&gates, g_gates);
    cudaGetSymbolAddress((void**)&hlast, g_hlast);
    cudaGetSymbolAddress((void**)&bias,  g_bias);

    cudaFuncSetAttribute(gemm_gates, cudaFuncAttributeMaxDynamicSharedMemorySize, SMEM_DYN);

    const size_t nwx = (size_t)GATES_N * INPUT_D;
    const size_t nwh = (size_t)GATES_N * HID;

    // setup: split x (*255); permute+split weights; combine+permute biases
    {
        const size_t nx = (size_t)STEPS * SEQ * INPUT_D;
        split_kernel<<<(unsigned)((nx + 255) / 256), 256>>>(x, xhi, xlo, nx, 255.0f);
        split_permute_w<<<(unsigned)((nwx + 255) / 256), 256>>>(w_ih1, wxh, wxl, 9);
        split_permute_w<<<(unsigned)((nwh + 255) / 256), 256>>>(w_hh1, whh, whl, 10);
        split_permute_w<<<(unsigned)((nwx + 255) / 256), 256>>>(w_ih2, wxh + nwx, wxl + nwx, 9);
        split_permute_w<<<(unsigned)((nwh + 255) / 256), 256>>>(w_hh2, whh + nwh, whl + nwh, 10);
        bias_combine<<<(GATES_N + 255) / 256, 256>>>(b_ih1, b_hh1, bias);
        bias_combine<<<(GATES_N + 255) / 256, 256>>>(b_ih2, b_hh2, bias + GATES_N);
    }
    zero_state_kernel<<<(SEQ * HID + 255) / 256, 256>>>();

    // PDL launch configs
    cudaLaunchAttribute pdl_attr[1];
    pdl_attr[0].id = cudaLaunchAttributeProgrammaticStreamSerialization;
    pdl_attr[0].val.programmaticStreamSerializationAllowed = 1;

    cudaLaunchConfig_t gemm_cfg = {};
    gemm_cfg.gridDim = dim3(GATES_N / TILE_N, SEQ / TILE_M, 1);   // (64, 16) = 1024 CTAs
    gemm_cfg.blockDim = dim3(128, 1, 1);
    gemm_cfg.dynamicSmemBytes = SMEM_DYN;
    gemm_cfg.stream = 0;
    gemm_cfg.attrs = pdl_attr;
    gemm_cfg.numAttrs = 1;

    cudaLaunchConfig_t cell_cfg = {};
    cell_cfg.gridDim = dim3((SEQ * HID) / 256, 1, 1);
    cell_cfg.blockDim = dim3(256, 1, 1);
    cell_cfg.dynamicSmemBytes = 0;
    cell_cfg.stream = 0;
    cell_cfg.attrs = pdl_attr;
    cell_cfg.numAttrs = 1;

    for (int t = 0; t < STEPS; ++t) {
        const __nv_bfloat16* xth = xhi + (size_t)t * SEQ * INPUT_D;
        const __nv_bfloat16* xtl = xlo + (size_t)t * SEQ * INPUT_D;
        float* hl = (float*)nullptr;

        cudaLaunchKernelEx(&gemm_cfg, gemm_gates,
                           xth, xtl,
                           (const __nv_bfloat16*)hhi, (const __nv_bfloat16*)hlo,
                           (const __nv_bfloat16*)wxh, (const __nv_bfloat16*)wxl,
                           (const __nv_bfloat16*)whh, (const __nv_bfloat16*)whl,
                           (const float*)bias, gates);
        cudaLaunchKernelEx(&cell_cfg, lstm_cell_kernel,
                           (const float*)gates, hhi, hlo, c, hl);

        cudaLaunchKernelEx(&gemm_cfg, gemm_gates,
                           xth, xtl,
                           (const __nv_bfloat16*)hhi, (const __nv_bfloat16*)hlo,
                           (const __nv_bfloat16*)(wxh + nwx), (const __nv_bfloat16*)(wxl + nwx),
                           (const __nv_bfloat16*)(whh + nwh), (const __nv_bfloat16*)(whl + nwh),
                           (const float*)(bias + GATES_N), gates);
        float* hl2 = hlast + (size_t)t * HID;
        cudaLaunchKernelEx(&cell_cfg, lstm_cell_kernel,
                           (const float*)gates, hhi, hlo, c, hl2);
    }

    fc_kernel<<<STEPS, 256>>>(hlast, w_fc, b_fc, out);
}

// round 15
// speedup vs baseline: 1.1418x; 1.0405x over previous
#include <cuda_runtime.h>
#include <cuda_bf16.h>
#include <cstdint>
#include <math.h>

#define SEQ     1024
#define INPUT_D 512
#define HID     1024
#define GATES_N 4096
#define STEPS   128
#define OUT_D   1000

// ---------------- device scratch ----------------
__device__ __nv_bfloat16 g_xhi[(size_t)STEPS * SEQ * INPUT_D];
__device__ __nv_bfloat16 g_xlo[(size_t)STEPS * SEQ * INPUT_D];
__device__ __nv_bfloat16 g_wxh[2][GATES_N * INPUT_D];   // gate-interleaved rows
__device__ __nv_bfloat16 g_wxl[2][GATES_N * INPUT_D];
__device__ __nv_bfloat16 g_whh[2][GATES_N * HID];
__device__ __nv_bfloat16 g_whl[2][GATES_N * HID];
__device__ float g_bias[2][GATES_N];                     // permuted b_ih + b_hh
__device__ __nv_bfloat16 g_hhi[2][SEQ * HID];            // ping-pong h
__device__ __nv_bfloat16 g_hlo[2][SEQ * HID];
__device__ float g_c[SEQ * HID];
__device__ float g_hlast[STEPS * HID];

// ---------------- helpers ----------------
__device__ __forceinline__ uint32_t smem_u32(const void* p) {
    return (uint32_t)__cvta_generic_to_shared(p);
}
__device__ __forceinline__ void cp16(uint32_t saddr, const void* gaddr) {
    asm volatile("cp.async.cg.shared.global [%0], [%1], 16;" :: "r"(saddr), "l"(gaddr) : "memory");
}
#define CP_COMMIT() asm volatile("cp.async.commit_group;" ::: "memory")
#define CP_WAIT(n)  asm volatile("cp.async.wait_group %0;" :: "n"(n) : "memory")

__device__ __forceinline__ uint32_t sw128(uint32_t off) {
    return off ^ ((off >> 3) & 0x70);
}

// ---------------- fused GEMM+cell: 64x64 tiles, 1024 jobs, occ 4 -------------
#define TILE_M   64
#define TILE_N   64
#define SUP_K    32
#define NS       3
#define NRANGES  48          // 16 x-ranges (K=512) + 32 h-ranges (K=1024)
#define FIRST_H  16
#define AB_BYTES 8192        // A-comb (or B-comb): 64 rows x 128B (hi|lo)
#define STAGE_BYTES (2 * AB_BYTES)   // 16 KB
#define SMEM_DYN (NS * STAGE_BYTES)  // 48 KB -> 4 CTAs/SM
#define EROW     68                   // staged gate-tile row stride (floats; 272B, 16B-aligned)

#define MMA4(ACC, BSRC) \
    asm volatile( \
        "mma.sync.aligned.m16n8k16.row.col.f32.bf16.bf16.f32 " \
        "{%0,%1,%2,%3}, {%4,%5,%6,%7}, {%8,%9}, {%0,%1,%2,%3};" \
        : "+f"(ACC[mt][nt][0]), "+f"(ACC[mt][nt][1]), \
          "+f"(ACC[mt][nt][2]), "+f"(ACC[mt][nt][3]) \
        : "r"(a0), "r"(a1), "r"(a2), "r"(a3), \
          "r"(BSRC[nt][0]), "r"(BSRC[nt][1]));

__global__ __launch_bounds__(128, 4)
void gemm_lstm(const __nv_bfloat16* __restrict__ xhi, const __nv_bfloat16* __restrict__ xlo,
               const __nv_bfloat16* __restrict__ hhi, const __nv_bfloat16* __restrict__ hlo,
               const __nv_bfloat16* __restrict__ wxh, const __nv_bfloat16* __restrict__ wxl,
               const __nv_bfloat16* __restrict__ whh, const __nv_bfloat16* __restrict__ whl,
               const float* __restrict__ bsum,
               float* __restrict__ c,
               __nv_bfloat16* __restrict__ hhi_w, __nv_bfloat16* __restrict__ hlo_w,
               float* __restrict__ hlast)
{
    extern __shared__ __align__(1024) char smem_raw[];
    const uint32_t sbase = smem_u32(smem_raw);

    const int tid = threadIdx.x;
    const int wid = tid >> 5;
    const int lane = tid & 31;
    const int wm = wid & 1;          // 2 warps along M (32 rows)
    const int wn = wid >> 1;         // 2 warps along N (32 cols)
    const int bn = blockIdx.x * TILE_N;
    const int bm = blockIdx.y * TILE_M;

    auto load_range = [&](int rr, int stage) {
        const bool isx = rr < FIRST_H;
        const int kst = isx ? INPUT_D : HID;
        const int k0 = (isx ? rr : rr - FIRST_H) * SUP_K;
        const __nv_bfloat16* pah = isx ? xhi : hhi;
        const __nv_bfloat16* pal = isx ? xlo : hlo;
        const __nv_bfloat16* pbh = isx ? wxh : whh;
        const __nv_bfloat16* pbl = isx ? wxl : whl;
        const uint32_t abase = sbase + stage * STAGE_BYTES;
        const uint32_t bbase = abase + AB_BYTES;
#pragma unroll
        for (int v = 0; v < 2; v++) {
            const int w = v * 128 + tid;
            const int row = w >> 2;
            const int c4 = (w & 3) * 16;
            const int kk = k0 + c4 / 2;
            cp16(abase + sw128(row * 128 + c4),      pah + (size_t)(bm + row) * kst + kk);
            cp16(abase + sw128(row * 128 + 64 + c4), pal + (size_t)(bm + row) * kst + kk);
            cp16(bbase + sw128(row * 128 + c4),      pbh + (size_t)(bn + row) * kst + kk);
            cp16(bbase + sw128(row * 128 + 64 + c4), pbl + (size_t)(bn + row) * kst + kk);
        }
    };

    float acc[2][4][4];
#pragma unroll
    for (int i = 0; i < 2; i++)
#pragma unroll
        for (int j = 0; j < 4; j++)
#pragma unroll
            for (int q = 0; q < 4; q++) acc[i][j][q] = 0.0f;

    auto compute_stage = [&](int stage) {
        const uint32_t abase = sbase + stage * STAGE_BYTES;
        const uint32_t bbase = abase + AB_BYTES;
        const int g = lane >> 3, l7 = lane & 7;
        const int arow = wm * 32 + (lane & 15);
        const int acol = (lane >> 4) * 16;
#pragma unroll
        for (int ks = 0; ks < 2; ks++) {
            uint32_t bh[4][2], bl[4][2];
#pragma unroll
            for (int ntp = 0; ntp < 2; ntp++) {
                const int nrow = wn * 32 + ntp * 16 + ((g >> 1) << 3) + l7;
                const uint32_t ah = bbase + sw128(nrow * 128 + ks * 32 + (g & 1) * 16);
                asm volatile("ldmatrix.sync.aligned.m8n8.x4.shared.b16 {%0,%1,%2,%3}, [%4];"
                    : "=r"(bh[ntp * 2][0]), "=r"(bh[ntp * 2][1]),
                      "=r"(bh[ntp * 2 + 1][0]), "=r"(bh[ntp * 2 + 1][1])
                    : "r"(ah));
                const uint32_t al = bbase + sw128(nrow * 128 + 64 + ks * 32 + (g & 1) * 16);
                asm volatile("ldmatrix.sync.aligned.m8n8.x4.shared.b16 {%0,%1,%2,%3}, [%4];"
                    : "=r"(bl[ntp * 2][0]), "=r"(bl[ntp * 2][1]),
                      "=r"(bl[ntp * 2 + 1][0]), "=r"(bl[ntp * 2 + 1][1])
                    : "r"(al));
            }
#pragma unroll
            for (int mt = 0; mt < 2; mt++) {
                const int mrow = arow + mt * 16;
                const uint32_t aa = abase + sw128(mrow * 128 + ks * 32 + acol);
                uint32_t a0, a1, a2, a3;
                asm volatile("ldmatrix.sync.aligned.m8n8.x4.shared.b16 {%0,%1,%2,%3}, [%4];"
                    : "=r"(a0), "=r"(a1), "=r"(a2), "=r"(a3) : "r"(aa));
#pragma unroll
                for (int nt = 0; nt < 4; nt++) { MMA4(acc, bh) }
#pragma unroll
                for (int nt = 0; nt < 4; nt++) { MMA4(acc, bl) }
            }
#pragma unroll
            for (int mt = 0; mt < 2; mt++) {
                const int mrow = arow + mt * 16;
                const uint32_t aa = abase + sw128(mrow * 128 + 64 + ks * 32 + acol);
                uint32_t a0, a1, a2, a3;
                asm volatile("ldmatrix.sync.aligned.m8n8.x4.shared.b16 {%0,%1,%2,%3}, [%4];"
                    : "=r"(a0), "=r"(a1), "=r"(a2), "=r"(a3) : "r"(aa));
#pragma unroll
                for (int nt = 0; nt < 4; nt++) { MMA4(acc, bh) }
            }
        }
    };

    // prologue: ranges 0..NS-2 are x-ranges (no dependency on upstream kernel)
#pragma unroll
    for (int p = 0; p < NS - 1; p++) { load_range(p, p); CP_COMMIT(); }

#pragma unroll 1
    for (int i = 0; i < NRANGES; i++) {
        CP_WAIT(NS - 2);
        __syncthreads();
        const int nc = i + NS - 1;
        if (nc < NRANGES) {
            if (nc == FIRST_H)
                cudaGridDependencySynchronize();   // upstream grid fully done: h final
            load_range(nc, nc % NS);
        }
        CP_COMMIT();
        compute_stage(i % NS);
    }

    // next grid may launch; its gridDepSync still waits for our full completion
    cudaTriggerProgrammaticLaunchCompletion();

    // ---------------- fused epilogue: stage gates (+bias) in smem ------------
    CP_WAIT(0);
    __syncthreads();                 // pipeline smem dead; reuse for gate tile
    float* sg = reinterpret_cast<float*>(smem_raw);   // [64][EROW]

#pragma unroll
    for (int mt = 0; mt < 2; mt++) {
        const int r0 = wm * 32 + mt * 16 + (lane >> 2);
        const int nl = wn * 32 + (lane & 3) * 2;
#pragma unroll
        for (int nt = 0; nt < 4; nt++) {
            const int col = nl + nt * 8;
            const int n0 = bn + col;
            const float bs0 = bsum[n0];
            const float bs1 = bsum[n0 + 1];
            float* p0 = sg + r0 * EROW + col;
            float* p1 = sg + (r0 + 8) * EROW + col;
            p0[0] = acc[mt][nt][0] + bs0; p0[1] = acc[mt][nt][1] + bs1;
            p1[0] = acc[mt][nt][2] + bs0; p1[1] = acc[mt][nt][3] + bs1;
        }
    }
    __syncthreads();

    // cell phase: 64 rows x 16 units, coalesced gmem (16 consecutive units/row)
    const int ubase = bn >> 2;
#pragma unroll
    for (int it = 0; it < 8; it++) {
        const int idx = it * 128 + tid;          // 0..1023
        const int ml = idx >> 4;                 // 0..63
        const int ul = idx & 15;                 // 0..15
        const float4 g4 = *reinterpret_cast<const float4*>(sg + ml * EROW + ul * 4);

        const int m = bm + ml;
        const int u = ubase + ul;
        const int gix = m * HID + u;

        const float co = c[gix];
        const float si = 1.0f / (1.0f + expf(-g4.x));
        const float sf = 1.0f / (1.0f + expf(-g4.y));
        const float tg = tanhf(g4.z);
        const float so = 1.0f / (1.0f + expf(-g4.w));
        const float cn = sf * co + si * tg;
        const float hn = so * tanhf(cn);
        c[gix] = cn;
        const __nv_bfloat16 hh = __float2bfloat16(hn);
        hhi_w[gix] = hh;
        hlo_w[gix] = __float2bfloat16(hn - __bfloat162float(hh));
        if (hlast != nullptr && m == SEQ - 1) hlast[u] = hn;
    }
}

// ---------------- setup kernels ----------------
__global__ void split_kernel(const float* __restrict__ src, __nv_bfloat16* __restrict__ hi,
                             __nv_bfloat16* __restrict__ lo, size_t n, float scale)
{
    const size_t i = (size_t)blockIdx.x * blockDim.x + threadIdx.x;
    if (i < n) {
        const float v = src[i] * scale;
        const __nv_bfloat16 h = __float2bfloat16(v);
        hi[i] = h;
        lo[i] = __float2bfloat16(v - __bfloat162float(h));
    }
}

// permute rows to gate-interleaved order: new_row = 4*unit + gate
__global__ void split_permute_w(const float* __restrict__ src, __nv_bfloat16* __restrict__ hi,
                                __nv_bfloat16* __restrict__ lo, int kshift)
{
    const size_t i = (size_t)blockIdx.x * blockDim.x + threadIdx.x;
    const int K = 1 << kshift;
    if (i < (size_t)GATES_N << kshift) {
        const int row = (int)(i >> kshift);
        const int k = (int)(i & (K - 1));
        const int nrow = ((row & 1023) << 2) | (row >> 10);
        const float v = src[i];
        const __nv_bfloat16 h = __float2bfloat16(v);
        hi[(size_t)nrow * K + k] = h;
        lo[(size_t)nrow * K + k] = __float2bfloat16(v - __bfloat162float(h));
    }
}

__global__ void bias_combine(const float* __restrict__ b_ih, const float* __restrict__ b_hh,
                             float* __restrict__ bsum)
{
    const int i = blockIdx.x * blockDim.x + threadIdx.x;
    if (i < GATES_N) {
        const int ni = ((i & 1023) << 2) | (i >> 10);
        bsum[ni] = b_ih[i] + b_hh[i];
    }
}

__global__ void zero_state_kernel()
{
    const int i = blockIdx.x * blockDim.x + threadIdx.x;
    if (i < SEQ * HID) {
        g_hhi[0][i] = __float2bfloat16(0.f);
        g_hlo[0][i] = __float2bfloat16(0.f);
        g_hhi[1][i] = __float2bfloat16(0.f);
        g_hlo[1][i] = __float2bfloat16(0.f);
        g_c[i] = 0.f;
    }
}

__global__ __launch_bounds__(256)
void fc_kernel(const float* __restrict__ Hl, const float* __restrict__ Wfc,
               const float* __restrict__ bfc, float* __restrict__ out)
{
    __shared__ float hrow[HID];
    const int t = blockIdx.x;
    for (int k = threadIdx.x; k < HID; k += 256) hrow[k] = Hl[(size_t)t * HID + k];
    __syncthreads();
    for (int n = threadIdx.x; n < OUT_D; n += 256) {
        const float* w = Wfc + (size_t)n * HID;
        float s = 0.f;
#pragma unroll 8
        for (int k = 0; k < HID; k++) s = fmaf(hrow[k], w[k], s);
        out[(size_t)t * OUT_D + n] = s + bfc[n];
    }
}

// ---------------- launch ----------------
extern "C" void kernel_launch(void* const* d_in, const int* in_sizes, int n_in,
                              void* d_out, int out_size)
{
    const float* x     = (const float*)d_in[0];
    const float* w_ih1 = (const float*)d_in[1];
    const float* w_hh1 = (const float*)d_in[2];
    const float* b_ih1 = (const float*)d_in[3];
    const float* b_hh1 = (const float*)d_in[4];
    const float* w_ih2 = (const float*)d_in[5];
    const float* w_hh2 = (const float*)d_in[6];
    const float* b_ih2 = (const float*)d_in[7];
    const float* b_hh2 = (const float*)d_in[8];
    const float* w_fc  = (const float*)d_in[9];
    const float* b_fc  = (const float*)d_in[10];
    float* out = (float*)d_out;

    __nv_bfloat16 *xhi, *xlo, *wxh, *wxl, *whh, *whl, *hhi, *hlo;
    float *c, *hlast, *bias;
    cudaGetSymbolAddress((void**)&xhi, g_xhi);
    cudaGetSymbolAddress((void**)&xlo, g_xlo);
    cudaGetSymbolAddress((void**)&wxh, g_wxh);
    cudaGetSymbolAddress((void**)&wxl, g_wxl);
    cudaGetSymbolAddress((void**)&whh, g_whh);
    cudaGetSymbolAddress((void**)&whl, g_whl);
    cudaGetSymbolAddress((void**)&hhi, g_hhi);
    cudaGetSymbolAddress((void**)&hlo, g_hlo);
    cudaGetSymbolAddress((void**)&c,     g_c);
    cudaGetSymbolAddress((void**)&hlast, g_hlast);
    cudaGetSymbolAddress((void**)&bias,  g_bias);

    cudaFuncSetAttribute(gemm_lstm, cudaFuncAttributeMaxDynamicSharedMemorySize, SMEM_DYN);

    const size_t nwx = (size_t)GATES_N * INPUT_D;
    const size_t nwh = (size_t)GATES_N * HID;
    const size_t nh  = (size_t)SEQ * HID;

    // setup: split x (*255); permute+split weights; combine+permute biases
    {
        const size_t nx = (size_t)STEPS * SEQ * INPUT_D;
        split_kernel<<<(unsigned)((nx + 255) / 256), 256>>>(x, xhi, xlo, nx, 255.0f);
        split_permute_w<<<(unsigned)((nwx + 255) / 256), 256>>>(w_ih1, wxh, wxl, 9);
        split_permute_w<<<(unsigned)((nwh + 255) / 256), 256>>>(w_hh1, whh, whl, 10);
        split_permute_w<<<(unsigned)((nwx + 255) / 256), 256>>>(w_ih2, wxh + nwx, wxl + nwx, 9);
        split_permute_w<<<(unsigned)((nwh + 255) / 256), 256>>>(w_hh2, whh + nwh, whl + nwh, 10);
        bias_combine<<<(GATES_N + 255) / 256, 256>>>(b_ih1, b_hh1, bias);
        bias_combine<<<(GATES_N + 255) / 256, 256>>>(b_ih2, b_hh2, bias + GATES_N);
    }
    zero_state_kernel<<<(SEQ * HID + 255) / 256, 256>>>();

    // PDL launch config
    cudaLaunchAttribute pdl_attr[1];
    pdl_attr[0].id = cudaLaunchAttributeProgrammaticStreamSerialization;
    pdl_attr[0].val.programmaticStreamSerializationAllowed = 1;

    cudaLaunchConfig_t gemm_cfg = {};
    gemm_cfg.gridDim = dim3(GATES_N / TILE_N, SEQ / TILE_M, 1);   // (64, 16) = 1024 CTAs
    gemm_cfg.blockDim = dim3(128, 1, 1);
    gemm_cfg.dynamicSmemBytes = SMEM_DYN;
    gemm_cfg.stream = 0;
    gemm_cfg.attrs = pdl_attr;
    gemm_cfg.numAttrs = 1;

    for (int t = 0; t < STEPS; ++t) {
        const __nv_bfloat16* xth = xhi + (size_t)t * SEQ * INPUT_D;
        const __nv_bfloat16* xtl = xlo + (size_t)t * SEQ * INPUT_D;
        float* hl = (float*)nullptr;

        // layer 1: reads h[0], writes h[1]
        cudaLaunchKernelEx(&gemm_cfg, gemm_lstm,
                           xth, xtl,
                           (const __nv_bfloat16*)hhi, (const __nv_bfloat16*)hlo,
                           (const __nv_bfloat16*)wxh, (const __nv_bfloat16*)wxl,
                           (const __nv_bfloat16*)whh, (const __nv_bfloat16*)whl,
                           (const float*)bias, c,
                           hhi + nh, hlo + nh, hl);

        // layer 2: reads h[1], writes h[0]
        float* hl2 = hlast + (size_t)t * HID;
        cudaLaunchKernelEx(&gemm_cfg, gemm_lstm,
                           xth, xtl,
                           (const __nv_bfloat16*)(hhi + nh), (const __nv_bfloat16*)(hlo + nh),
                           (const __nv_bfloat16*)(wxh + nwx), (const __nv_bfloat16*)(wxl + nwx),
                           (const __nv_bfloat16*)(whh + nwh), (const __nv_bfloat16*)(whl + nwh),
                           (const float*)(bias + GATES_N), c,
                           hhi, hlo, hl2);
    }

    fc_kernel<<<STEPS, 256>>>(hlast, w_fc, b_fc, out);
}

// round 16
// speedup vs baseline: 1.1430x; 1.0010x over previous
#include <cuda_runtime.h>
#include <cuda_bf16.h>
#include <cstdint>
#include <math.h>

#define SEQ     1024
#define INPUT_D 512
#define HID     1024
#define GATES_N 4096
#define STEPS   128
#define OUT_D   1000

// ---------------- device scratch ----------------
__device__ __nv_bfloat16 g_xhi[(size_t)STEPS * SEQ * INPUT_D];
__device__ __nv_bfloat16 g_xlo[(size_t)STEPS * SEQ * INPUT_D];
__device__ __nv_bfloat16 g_wxh[2][GATES_N * INPUT_D];   // gate-interleaved rows
__device__ __nv_bfloat16 g_wxl[2][GATES_N * INPUT_D];
__device__ __nv_bfloat16 g_whh[2][GATES_N * HID];
__device__ __nv_bfloat16 g_whl[2][GATES_N * HID];
__device__ float g_bias[2][GATES_N];                     // permuted b_ih + b_hh
__device__ __nv_bfloat16 g_hhi[2][SEQ * HID];            // ping-pong h
__device__ __nv_bfloat16 g_hlo[2][SEQ * HID];
__device__ float g_c[SEQ * HID];
__device__ float g_hlast[STEPS * HID];

// ---------------- helpers ----------------
__device__ __forceinline__ uint32_t smem_u32(const void* p) {
    return (uint32_t)__cvta_generic_to_shared(p);
}
__device__ __forceinline__ void cp16(uint32_t saddr, const void* gaddr) {
    asm volatile("cp.async.cg.shared.global [%0], [%1], 16;" :: "r"(saddr), "l"(gaddr) : "memory");
}
#define CP_COMMIT() asm volatile("cp.async.commit_group;" ::: "memory")
#define CP_WAIT(n)  asm volatile("cp.async.wait_group %0;" :: "n"(n) : "memory")

__device__ __forceinline__ uint32_t sw128(uint32_t off) {
    return off ^ ((off >> 3) & 0x70);
}

// ---------------- fused GEMM+cell: 64x64 tiles, 1024 jobs, occ 4 -------------
#define TILE_M   64
#define TILE_N   64
#define SUP_K    32
#define NS       3
#define NRANGES  48          // 16 x-ranges (K=512) + 32 h-ranges (K=1024)
#define FIRST_H  16
#define AB_BYTES 8192        // A-comb (or B-comb): 64 rows x 128B (hi|lo)
#define STAGE_BYTES (2 * AB_BYTES)   // 16 KB
#define SMEM_DYN (NS * STAGE_BYTES)  // 48 KB -> 4 CTAs/SM
#define EROW     68                   // staged gate-tile row stride (floats)

#define MMA4(ACC, BSRC) \
    asm volatile( \
        "mma.sync.aligned.m16n8k16.row.col.f32.bf16.bf16.f32 " \
        "{%0,%1,%2,%3}, {%4,%5,%6,%7}, {%8,%9}, {%0,%1,%2,%3};" \
        : "+f"(ACC[mt][nt][0]), "+f"(ACC[mt][nt][1]), \
          "+f"(ACC[mt][nt][2]), "+f"(ACC[mt][nt][3]) \
        : "r"(a0), "r"(a1), "r"(a2), "r"(a3), \
          "r"(BSRC[nt][0]), "r"(BSRC[nt][1]));

// load all 4 B sub-fragments (hi+lo, both 16-col groups) for one ks half
#define LDB(KS, BH, BL) \
    _Pragma("unroll") \
    for (int ntp = 0; ntp < 2; ntp++) { \
        const int nrow = wn * 32 + ntp * 16 + ((g >> 1) << 3) + l7; \
        const uint32_t ah = bbase + sw128(nrow * 128 + (KS) * 32 + (g & 1) * 16); \
        asm volatile("ldmatrix.sync.aligned.m8n8.x4.shared.b16 {%0,%1,%2,%3}, [%4];" \
            : "=r"(BH[ntp * 2][0]), "=r"(BH[ntp * 2][1]), \
              "=r"(BH[ntp * 2 + 1][0]), "=r"(BH[ntp * 2 + 1][1]) \
            : "r"(ah)); \
        const uint32_t al = bbase + sw128(nrow * 128 + 64 + (KS) * 32 + (g & 1) * 16); \
        asm volatile("ldmatrix.sync.aligned.m8n8.x4.shared.b16 {%0,%1,%2,%3}, [%4];" \
            : "=r"(BL[ntp * 2][0]), "=r"(BL[ntp * 2][1]), \
              "=r"(BL[ntp * 2 + 1][0]), "=r"(BL[ntp * 2 + 1][1]) \
            : "r"(al)); \
    }

// MMA body for one ks half using given B fragments
#define KS_BODY(KS, BH, BL) \
    _Pragma("unroll") \
    for (int mt = 0; mt < 2; mt++) { \
        const int mrow = arow + mt * 16; \
        const uint32_t aa = abase + sw128(mrow * 128 + (KS) * 32 + acol); \
        uint32_t a0, a1, a2, a3; \
        asm volatile("ldmatrix.sync.aligned.m8n8.x4.shared.b16 {%0,%1,%2,%3}, [%4];" \
            : "=r"(a0), "=r"(a1), "=r"(a2), "=r"(a3) : "r"(aa)); \
        _Pragma("unroll") \
        for (int nt = 0; nt < 4; nt++) { MMA4(acc, BH) } \
        _Pragma("unroll") \
        for (int nt = 0; nt < 4; nt++) { MMA4(acc, BL) } \
    } \
    _Pragma("unroll") \
    for (int mt = 0; mt < 2; mt++) { \
        const int mrow = arow + mt * 16; \
        const uint32_t aa = abase + sw128(mrow * 128 + 64 + (KS) * 32 + acol); \
        uint32_t a0, a1, a2, a3; \
        asm volatile("ldmatrix.sync.aligned.m8n8.x4.shared.b16 {%0,%1,%2,%3}, [%4];" \
            : "=r"(a0), "=r"(a1), "=r"(a2), "=r"(a3) : "r"(aa)); \
        _Pragma("unroll") \
        for (int nt = 0; nt < 4; nt++) { MMA4(acc, BH) } \
    }

__global__ __launch_bounds__(128, 4)
void gemm_lstm(const __nv_bfloat16* __restrict__ xhi, const __nv_bfloat16* __restrict__ xlo,
               const __nv_bfloat16* __restrict__ hhi, const __nv_bfloat16* __restrict__ hlo,
               const __nv_bfloat16* __restrict__ wxh, const __nv_bfloat16* __restrict__ wxl,
               const __nv_bfloat16* __restrict__ whh, const __nv_bfloat16* __restrict__ whl,
               const float* __restrict__ bsum,
               float* __restrict__ c,
               __nv_bfloat16* __restrict__ hhi_w, __nv_bfloat16* __restrict__ hlo_w,
               float* __restrict__ hlast)
{
    extern __shared__ __align__(1024) char smem_raw[];
    const uint32_t sbase = smem_u32(smem_raw);

    const int tid = threadIdx.x;
    const int wid = tid >> 5;
    const int lane = tid & 31;
    const int wm = wid & 1;          // 2 warps along M (32 rows)
    const int wn = wid >> 1;         // 2 warps along N (32 cols)
    const int bn = blockIdx.x * TILE_N;
    const int bm = blockIdx.y * TILE_M;

    auto load_range = [&](int rr, int stage) {
        const bool isx = rr < FIRST_H;
        const int kst = isx ? INPUT_D : HID;
        const int k0 = (isx ? rr : rr - FIRST_H) * SUP_K;
        const __nv_bfloat16* pah = isx ? xhi : hhi;
        const __nv_bfloat16* pal = isx ? xlo : hlo;
        const __nv_bfloat16* pbh = isx ? wxh : whh;
        const __nv_bfloat16* pbl = isx ? wxl : whl;
        const uint32_t abase = sbase + stage * STAGE_BYTES;
        const uint32_t bbase = abase + AB_BYTES;
#pragma unroll
        for (int v = 0; v < 2; v++) {
            const int w = v * 128 + tid;
            const int row = w >> 2;
            const int c4 = (w & 3) * 16;
            const int kk = k0 + c4 / 2;
            cp16(abase + sw128(row * 128 + c4),      pah + (size_t)(bm + row) * kst + kk);
            cp16(abase + sw128(row * 128 + 64 + c4), pal + (size_t)(bm + row) * kst + kk);
            cp16(bbase + sw128(row * 128 + c4),      pbh + (size_t)(bn + row) * kst + kk);
            cp16(bbase + sw128(row * 128 + 64 + c4), pbl + (size_t)(bn + row) * kst + kk);
        }
    };

    float acc[2][4][4];
#pragma unroll
    for (int i = 0; i < 2; i++)
#pragma unroll
        for (int j = 0; j < 4; j++)
#pragma unroll
            for (int q = 0; q < 4; q++) acc[i][j][q] = 0.0f;

    // software-pipelined superstage: hoist all B-ldsm (both ks halves) up front
    auto compute_stage = [&](int stage) {
        const uint32_t abase = sbase + stage * STAGE_BYTES;
        const uint32_t bbase = abase + AB_BYTES;
        const int g = lane >> 3, l7 = lane & 7;
        const int arow = wm * 32 + (lane & 15);
        const int acol = (lane >> 4) * 16;

        uint32_t bh0[4][2], bl0[4][2], bh1[4][2], bl1[4][2];
        LDB(0, bh0, bl0)
        LDB(1, bh1, bl1)
        KS_BODY(0, bh0, bl0)
        KS_BODY(1, bh1, bl1)
    };

    // prologue: ranges 0..NS-2 are x-ranges (no dependency on upstream kernel)
#pragma unroll
    for (int p = 0; p < NS - 1; p++) { load_range(p, p); CP_COMMIT(); }

#pragma unroll 1
    for (int i = 0; i < NRANGES; i++) {
        CP_WAIT(NS - 2);
        __syncthreads();
        const int nc = i + NS - 1;
        if (nc < NRANGES) {
            if (nc == FIRST_H)
                cudaGridDependencySynchronize();   // upstream grid fully done: h final
            load_range(nc, nc % NS);
        }
        CP_COMMIT();
        compute_stage(i % NS);
    }

    cudaTriggerProgrammaticLaunchCompletion();

    // ---------------- fused epilogue: stage gates (+bias) in smem ------------
    CP_WAIT(0);
    __syncthreads();
    float* sg = reinterpret_cast<float*>(smem_raw);   // [64][EROW]

#pragma unroll
    for (int mt = 0; mt < 2; mt++) {
        const int r0 = wm * 32 + mt * 16 + (lane >> 2);
        const int nl = wn * 32 + (lane & 3) * 2;
#pragma unroll
        for (int nt = 0; nt < 4; nt++) {
            const int col = nl + nt * 8;
            const int n0 = bn + col;
            const float bs0 = bsum[n0];
            const float bs1 = bsum[n0 + 1];
            float* p0 = sg + r0 * EROW + col;
            float* p1 = sg + (r0 + 8) * EROW + col;
            p0[0] = acc[mt][nt][0] + bs0; p0[1] = acc[mt][nt][1] + bs1;
            p1[0] = acc[mt][nt][2] + bs0; p1[1] = acc[mt][nt][3] + bs1;
        }
    }
    __syncthreads();

    // cell phase: 64 rows x 16 units, coalesced gmem
    const int ubase = bn >> 2;
#pragma unroll
    for (int it = 0; it < 8; it++) {
        const int idx = it * 128 + tid;          // 0..1023
        const int ml = idx >> 4;                 // 0..63
        const int ul = idx & 15;                 // 0..15
        const float4 g4 = *reinterpret_cast<const float4*>(sg + ml * EROW + ul * 4);

        const int m = bm + ml;
        const int u = ubase + ul;
        const int gix = m * HID + u;

        const float co = c[gix];
        const float si = 1.0f / (1.0f + expf(-g4.x));
        const float sf = 1.0f / (1.0f + expf(-g4.y));
        const float tg = tanhf(g4.z);
        const float so = 1.0f / (1.0f + expf(-g4.w));
        const float cn = sf * co + si * tg;
        const float hn = so * tanhf(cn);
        c[gix] = cn;
        const __nv_bfloat16 hh = __float2bfloat16(hn);
        hhi_w[gix] = hh;
        hlo_w[gix] = __float2bfloat16(hn - __bfloat162float(hh));
        if (hlast != nullptr && m == SEQ - 1) hlast[u] = hn;
    }
}

// ---------------- setup kernels ----------------
__global__ void split_kernel(const float* __restrict__ src, __nv_bfloat16* __restrict__ hi,
                             __nv_bfloat16* __restrict__ lo, size_t n, float scale)
{
    const size_t i = (size_t)blockIdx.x * blockDim.x + threadIdx.x;
    if (i < n) {
        const float v = src[i] * scale;
        const __nv_bfloat16 h = __float2bfloat16(v);
        hi[i] = h;
        lo[i] = __float2bfloat16(v - __bfloat162float(h));
    }
}

// permute rows to gate-interleaved order: new_row = 4*unit + gate
__global__ void split_permute_w(const float* __restrict__ src, __nv_bfloat16* __restrict__ hi,
                                __nv_bfloat16* __restrict__ lo, int kshift)
{
    const size_t i = (size_t)blockIdx.x * blockDim.x + threadIdx.x;
    const int K = 1 << kshift;
    if (i < (size_t)GATES_N << kshift) {
        const int row = (int)(i >> kshift);
        const int k = (int)(i & (K - 1));
        const int nrow = ((row & 1023) << 2) | (row >> 10);
        const float v = src[i];
        const __nv_bfloat16 h = __float2bfloat16(v);
        hi[(size_t)nrow * K + k] = h;
        lo[(size_t)nrow * K + k] = __float2bfloat16(v - __bfloat162float(h));
    }
}

__global__ void bias_combine(const float* __restrict__ b_ih, const float* __restrict__ b_hh,
                             float* __restrict__ bsum)
{
    const int i = blockIdx.x * blockDim.x + threadIdx.x;
    if (i < GATES_N) {
        const int ni = ((i & 1023) << 2) | (i >> 10);
        bsum[ni] = b_ih[i] + b_hh[i];
    }
}

__global__ void zero_state_kernel()
{
    const int i = blockIdx.x * blockDim.x + threadIdx.x;
    if (i < SEQ * HID) {
        g_hhi[0][i] = __float2bfloat16(0.f);
        g_hlo[0][i] = __float2bfloat16(0.f);
        g_hhi[1][i] = __float2bfloat16(0.f);
        g_hlo[1][i] = __float2bfloat16(0.f);
        g_c[i] = 0.f;
    }
}

__global__ __launch_bounds__(256)
void fc_kernel(const float* __restrict__ Hl, const float* __restrict__ Wfc,
               const float* __restrict__ bfc, float* __restrict__ out)
{
    __shared__ float hrow[HID];
    const int t = blockIdx.x;
    for (int k = threadIdx.x; k < HID; k += 256) hrow[k] = Hl[(size_t)t * HID + k];
    __syncthreads();
    for (int n = threadIdx.x; n < OUT_D; n += 256) {
        const float* w = Wfc + (size_t)n * HID;
        float s = 0.f;
#pragma unroll 8
        for (int k = 0; k < HID; k++) s = fmaf(hrow[k], w[k], s);
        out[(size_t)t * OUT_D + n] = s + bfc[n];
    }
}

// ---------------- launch ----------------
extern "C" void kernel_launch(void* const* d_in, const int* in_sizes, int n_in,
                              void* d_out, int out_size)
{
    const float* x     = (const float*)d_in[0];
    const float* w_ih1 = (const float*)d_in[1];
    const float* w_hh1 = (const float*)d_in[2];
    const float* b_ih1 = (const float*)d_in[3];
    const float* b_hh1 = (const float*)d_in[4];
    const float* w_ih2 = (const float*)d_in[5];
    const float* w_hh2 = (const float*)d_in[6];
    const float* b_ih2 = (const float*)d_in[7];
    const float* b_hh2 = (const float*)d_in[8];
    const float* w_fc  = (const float*)d_in[9];
    const float* b_fc  = (const float*)d_in[10];
    float* out = (float*)d_out;

    __nv_bfloat16 *xhi, *xlo, *wxh, *wxl, *whh, *whl, *hhi, *hlo;
    float *c, *hlast, *bias;
    cudaGetSymbolAddress((void**)&xhi, g_xhi);
    cudaGetSymbolAddress((void**)&xlo, g_xlo);
    cudaGetSymbolAddress((void**)&wxh, g_wxh);
    cudaGetSymbolAddress((void**)&wxl, g_wxl);
    cudaGetSymbolAddress((void**)&whh, g_whh);
    cudaGetSymbolAddress((void**)&whl, g_whl);
    cudaGetSymbolAddress((void**)&hhi, g_hhi);
    cudaGetSymbolAddress((void**)&hlo, g_hlo);
    cudaGetSymbolAddress((void**)&c,     g_c);
    cudaGetSymbolAddress((void**)&hlast, g_hlast);
    cudaGetSymbolAddress((void**)&bias,  g_bias);

    cudaFuncSetAttribute(gemm_lstm, cudaFuncAttributeMaxDynamicSharedMemorySize, SMEM_DYN);

    const size_t nwx = (size_t)GATES_N * INPUT_D;
    const size_t nwh = (size_t)GATES_N * HID;
    const size_t nh  = (size_t)SEQ * HID;

    // setup: split x (*255); permute+split weights; combine+permute biases
    {
        const size_t nx = (size_t)STEPS * SEQ * INPUT_D;
        split_kernel<<<(unsigned)((nx + 255) / 256), 256>>>(x, xhi, xlo, nx, 255.0f);
        split_permute_w<<<(unsigned)((nwx + 255) / 256), 256>>>(w_ih1, wxh, wxl, 9);
        split_permute_w<<<(unsigned)((nwh + 255) / 256), 256>>>(w_hh1, whh, whl, 10);
        split_permute_w<<<(unsigned)((nwx + 255) / 256), 256>>>(w_ih2, wxh + nwx, wxl + nwx, 9);
        split_permute_w<<<(unsigned)((nwh + 255) / 256), 256>>>(w_hh2, whh + nwh, whl + nwh, 10);
        bias_combine<<<(GATES_N + 255) / 256, 256>>>(b_ih1, b_hh1, bias);
        bias_combine<<<(GATES_N + 255) / 256, 256>>>(b_ih2, b_hh2, bias + GATES_N);
    }
    zero_state_kernel<<<(SEQ * HID + 255) / 256, 256>>>();

    // PDL launch config
    cudaLaunchAttribute pdl_attr[1];
    pdl_attr[0].id = cudaLaunchAttributeProgrammaticStreamSerialization;
    pdl_attr[0].val.programmaticStreamSerializationAllowed = 1;

    cudaLaunchConfig_t gemm_cfg = {};
    gemm_cfg.gridDim = dim3(GATES_N / TILE_N, SEQ / TILE_M, 1);   // (64, 16) = 1024 CTAs
    gemm_cfg.blockDim = dim3(128, 1, 1);
    gemm_cfg.dynamicSmemBytes = SMEM_DYN;
    gemm_cfg.stream = 0;
    gemm_cfg.attrs = pdl_attr;
    gemm_cfg.numAttrs = 1;

    for (int t = 0; t < STEPS; ++t) {
        const __nv_bfloat16* xth = xhi + (size_t)t * SEQ * INPUT_D;
        const __nv_bfloat16* xtl = xlo + (size_t)t * SEQ * INPUT_D;
        float* hl = (float*)nullptr;

        // layer 1: reads h[0], writes h[1]
        cudaLaunchKernelEx(&gemm_cfg, gemm_lstm,
                           xth, xtl,
                           (const __nv_bfloat16*)hhi, (const __nv_bfloat16*)hlo,
                           (const __nv_bfloat16*)wxh, (const __nv_bfloat16*)wxl,
                           (const __nv_bfloat16*)whh, (const __nv_bfloat16*)whl,
                           (const float*)bias, c,
                           hhi + nh, hlo + nh, hl);

        // layer 2: reads h[1], writes h[0]
        float* hl2 = hlast + (size_t)t * HID;
        cudaLaunchKernelEx(&gemm_cfg, gemm_lstm,
                           xth, xtl,
                           (const __nv_bfloat16*)(hhi + nh), (const __nv_bfloat16*)(hlo + nh),
                           (const __nv_bfloat16*)(wxh + nwx), (const __nv_bfloat16*)(wxl + nwx),
                           (const __nv_bfloat16*)(whh + nwh), (const __nv_bfloat16*)(whl + nwh),
                           (const float*)(bias + GATES_N), c,
                           hhi, hlo, hl2);
    }

    fc_kernel<<<STEPS, 256>>>(hlast, w_fc, b_fc, out);
}

// round 17
// speedup vs baseline: 1.7767x; 1.5545x over previous
#include <cuda_runtime.h>
#include <cuda_bf16.h>
#include <cuda_fp16.h>
#include <cstdint>
#include <math.h>

#define SEQ     1024
#define INPUT_D 512
#define HID     1024
#define GATES_N 4096
#define STEPS   128
#define OUT_D   1000

// ---------------- device scratch ----------------
__device__ __nv_bfloat16 g_xhi[(size_t)STEPS * SEQ * INPUT_D];
__device__ __nv_bfloat16 g_xlo[(size_t)STEPS * SEQ * INPUT_D];
__device__ __nv_bfloat16 g_wxh[2][GATES_N * INPUT_D];   // gate-interleaved rows (bf16 hi)
__device__ __nv_bfloat16 g_wxl[2][GATES_N * INPUT_D];   // bf16 lo
__device__ __half g_whf[2][GATES_N * HID];               // W_hh single fp16, gate-interleaved
__device__ __half g_hf[2][SEQ * HID];                    // ping-pong h, single fp16
__device__ float g_bias[2][GATES_N];                     // permuted b_ih + b_hh
__device__ float g_c[SEQ * HID];
__device__ float g_hlast[STEPS * HID];

// ---------------- helpers ----------------
__device__ __forceinline__ uint32_t smem_u32(const void* p) {
    return (uint32_t)__cvta_generic_to_shared(p);
}
__device__ __forceinline__ void cp16(uint32_t saddr, const void* gaddr) {
    asm volatile("cp.async.cg.shared.global [%0], [%1], 16;" :: "r"(saddr), "l"(gaddr) : "memory");
}
#define CP_COMMIT() asm volatile("cp.async.commit_group;" ::: "memory")
#define CP_WAIT(n)  asm volatile("cp.async.wait_group %0;" :: "n"(n) : "memory")

__device__ __forceinline__ uint32_t sw128(uint32_t off) {
    return off ^ ((off >> 3) & 0x70);
}

// ---------------- fused GEMM+cell: 64x64 tiles, mixed-precision emulation ----
// x-part: 16 ranges of K=32, bf16 3-product (hi|lo packed rows)  -> 48 MMA each
// h-part: 16 ranges of K=64, fp16 single product                -> 32 MMA each
#define TILE_M   64
#define TILE_N   64
#define NS       3
#define NRANGES  32
#define FIRST_H  16
#define AB_BYTES 8192        // 64 rows x 128B
#define STAGE_BYTES (2 * AB_BYTES)   // 16 KB
#define SMEM_DYN (NS * STAGE_BYTES)  // 48 KB -> 4 CTAs/SM
#define EROW     68                   // staged gate-tile row stride (floats)

#define MMA4BF(ACC, BSRC) \
    asm volatile( \
        "mma.sync.aligned.m16n8k16.row.col.f32.bf16.bf16.f32 " \
        "{%0,%1,%2,%3}, {%4,%5,%6,%7}, {%8,%9}, {%0,%1,%2,%3};" \
        : "+f"(ACC[mt][nt][0]), "+f"(ACC[mt][nt][1]), \
          "+f"(ACC[mt][nt][2]), "+f"(ACC[mt][nt][3]) \
        : "r"(a0), "r"(a1), "r"(a2), "r"(a3), \
          "r"(BSRC[nt][0]), "r"(BSRC[nt][1]));

#define MMA4F16(ACC, BSRC) \
    asm volatile( \
        "mma.sync.aligned.m16n8k16.row.col.f32.f16.f16.f32 " \
        "{%0,%1,%2,%3}, {%4,%5,%6,%7}, {%8,%9}, {%0,%1,%2,%3};" \
        : "+f"(ACC[mt][nt][0]), "+f"(ACC[mt][nt][1]), \
          "+f"(ACC[mt][nt][2]), "+f"(ACC[mt][nt][3]) \
        : "r"(a0), "r"(a1), "r"(a2), "r"(a3), \
          "r"(BSRC[nt][0]), "r"(BSRC[nt][1]));

__global__ __launch_bounds__(128, 4)
void gemm_lstm(const __nv_bfloat16* __restrict__ xhi, const __nv_bfloat16* __restrict__ xlo,
               const __half* __restrict__ hf,
               const __nv_bfloat16* __restrict__ wxh, const __nv_bfloat16* __restrict__ wxl,
               const __half* __restrict__ whf,
               const float* __restrict__ bsum,
               float* __restrict__ c,
               __half* __restrict__ hf_w,
               float* __restrict__ hlast)
{
    extern __shared__ __align__(1024) char smem_raw[];
    const uint32_t sbase = smem_u32(smem_raw);

    const int tid = threadIdx.x;
    const int wid = tid >> 5;
    const int lane = tid & 31;
    const int wm = wid & 1;          // 2 warps along M (32 rows)
    const int wn = wid >> 1;         // 2 warps along N (32 cols)
    const int bn = blockIdx.x * TILE_N;
    const int bm = blockIdx.y * TILE_M;

    auto load_range = [&](int rr, int stage) {
        const uint32_t abase = sbase + stage * STAGE_BYTES;
        const uint32_t bbase = abase + AB_BYTES;
        if (rr < FIRST_H) {
            // x-range: K=32 bf16, hi in bytes [0,64), lo in [64,128)
            const int k0 = rr * 32;
#pragma unroll
            for (int v = 0; v < 2; v++) {
                const int w = v * 128 + tid;
                const int row = w >> 2;
                const int c4 = (w & 3) * 16;
                const int kk = k0 + c4 / 2;
                cp16(abase + sw128(row * 128 + c4),      xhi + (size_t)(bm + row) * INPUT_D + kk);
                cp16(abase + sw128(row * 128 + 64 + c4), xlo + (size_t)(bm + row) * INPUT_D + kk);
                cp16(bbase + sw128(row * 128 + c4),      wxh + (size_t)(bn + row) * INPUT_D + kk);
                cp16(bbase + sw128(row * 128 + 64 + c4), wxl + (size_t)(bn + row) * INPUT_D + kk);
            }
        } else {
            // h-range: K=64 fp16, full 128B row
            const int k0 = (rr - FIRST_H) * 64;
#pragma unroll
            for (int v = 0; v < 4; v++) {
                const int w = v * 128 + tid;      // 0..511
                const int row = w >> 3;           // 0..63
                const int c8 = (w & 7) * 16;      // 0..112
                const int kk = k0 + c8 / 2;
                cp16(abase + sw128(row * 128 + c8), hf  + (size_t)(bm + row) * HID + kk);
                cp16(bbase + sw128(row * 128 + c8), whf + (size_t)(bn + row) * HID + kk);
            }
        }
    };

    float acc[2][4][4];
#pragma unroll
    for (int i = 0; i < 2; i++)
#pragma unroll
        for (int j = 0; j < 4; j++)
#pragma unroll
            for (int q = 0; q < 4; q++) acc[i][j][q] = 0.0f;

    auto compute_stage = [&](int rr, int stage) {
        const uint32_t abase = sbase + stage * STAGE_BYTES;
        const uint32_t bbase = abase + AB_BYTES;
        const int g = lane >> 3, l7 = lane & 7;
        const int arow = wm * 32 + (lane & 15);
        const int acol = (lane >> 4) * 16;

        if (rr < FIRST_H) {
            // x-range: 3 bf16 products over K=32 (2 ks halves)
#pragma unroll
            for (int ks = 0; ks < 2; ks++) {
                uint32_t bh[4][2], bl[4][2];
#pragma unroll
                for (int ntp = 0; ntp < 2; ntp++) {
                    const int nrow = wn * 32 + ntp * 16 + ((g >> 1) << 3) + l7;
                    const uint32_t ah = bbase + sw128(nrow * 128 + ks * 32 + (g & 1) * 16);
                    asm volatile("ldmatrix.sync.aligned.m8n8.x4.shared.b16 {%0,%1,%2,%3}, [%4];"
                        : "=r"(bh[ntp * 2][0]), "=r"(bh[ntp * 2][1]),
                          "=r"(bh[ntp * 2 + 1][0]), "=r"(bh[ntp * 2 + 1][1])
                        : "r"(ah));
                    const uint32_t al = bbase + sw128(nrow * 128 + 64 + ks * 32 + (g & 1) * 16);
                    asm volatile("ldmatrix.sync.aligned.m8n8.x4.shared.b16 {%0,%1,%2,%3}, [%4];"
                        : "=r"(bl[ntp * 2][0]), "=r"(bl[ntp * 2][1]),
                          "=r"(bl[ntp * 2 + 1][0]), "=r"(bl[ntp * 2 + 1][1])
                        : "r"(al));
                }
#pragma unroll
                for (int mt = 0; mt < 2; mt++) {
                    const int mrow = arow + mt * 16;
                    const uint32_t aa = abase + sw128(mrow * 128 + ks * 32 + acol);
                    uint32_t a0, a1, a2, a3;
                    asm volatile("ldmatrix.sync.aligned.m8n8.x4.shared.b16 {%0,%1,%2,%3}, [%4];"
                        : "=r"(a0), "=r"(a1), "=r"(a2), "=r"(a3) : "r"(aa));
#pragma unroll
                    for (int nt = 0; nt < 4; nt++) { MMA4BF(acc, bh) }
#pragma unroll
                    for (int nt = 0; nt < 4; nt++) { MMA4BF(acc, bl) }
                }
#pragma unroll
                for (int mt = 0; mt < 2; mt++) {
                    const int mrow = arow + mt * 16;
                    const uint32_t aa = abase + sw128(mrow * 128 + 64 + ks * 32 + acol);
                    uint32_t a0, a1, a2, a3;
                    asm volatile("ldmatrix.sync.aligned.m8n8.x4.shared.b16 {%0,%1,%2,%3}, [%4];"
                        : "=r"(a0), "=r"(a1), "=r"(a2), "=r"(a3) : "r"(aa));
#pragma unroll
                    for (int nt = 0; nt < 4; nt++) { MMA4BF(acc, bh) }
                }
            }
        } else {
            // h-range: single fp16 product over K=64 (4 ks chunks of k16)
#pragma unroll
            for (int ks = 0; ks < 4; ks++) {
                uint32_t bf[4][2];
#pragma unroll
                for (int ntp = 0; ntp < 2; ntp++) {
                    const int nrow = wn * 32 + ntp * 16 + ((g >> 1) << 3) + l7;
                    const uint32_t ba = bbase + sw128(nrow * 128 + ks * 32 + (g & 1) * 16);
                    asm volatile("ldmatrix.sync.aligned.m8n8.x4.shared.b16 {%0,%1,%2,%3}, [%4];"
                        : "=r"(bf[ntp * 2][0]), "=r"(bf[ntp * 2][1]),
                          "=r"(bf[ntp * 2 + 1][0]), "=r"(bf[ntp * 2 + 1][1])
                        : "r"(ba));
                }
#pragma unroll
                for (int mt = 0; mt < 2; mt++) {
                    const int mrow = arow + mt * 16;
                    const uint32_t aa = abase + sw128(mrow * 128 + ks * 32 + acol);
                    uint32_t a0, a1, a2, a3;
                    asm volatile("ldmatrix.sync.aligned.m8n8.x4.shared.b16 {%0,%1,%2,%3}, [%4];"
                        : "=r"(a0), "=r"(a1), "=r"(a2), "=r"(a3) : "r"(aa));
#pragma unroll
                    for (int nt = 0; nt < 4; nt++) { MMA4F16(acc, bf) }
                }
            }
        }
    };

    // prologue: ranges 0..NS-2 are x-ranges (no dependency on upstream kernel)
#pragma unroll
    for (int p = 0; p < NS - 1; p++) { load_range(p, p); CP_COMMIT(); }

#pragma unroll 1
    for (int i = 0; i < NRANGES; i++) {
        CP_WAIT(NS - 2);
        __syncthreads();
        const int nc = i + NS - 1;
        if (nc < NRANGES) {
            if (nc == FIRST_H)
                cudaGridDependencySynchronize();   // upstream grid fully done: h final
            load_range(nc, nc % NS);
        }
        CP_COMMIT();
        compute_stage(i, i % NS);
    }

    cudaTriggerProgrammaticLaunchCompletion();

    // ---------------- fused epilogue: stage gates (+bias) in smem ------------
    CP_WAIT(0);
    __syncthreads();
    float* sg = reinterpret_cast<float*>(smem_raw);   // [64][EROW]

#pragma unroll
    for (int mt = 0; mt < 2; mt++) {
        const int r0 = wm * 32 + mt * 16 + (lane >> 2);
        const int nl = wn * 32 + (lane & 3) * 2;
#pragma unroll
        for (int nt = 0; nt < 4; nt++) {
            const int col = nl + nt * 8;
            const int n0 = bn + col;
            const float bs0 = bsum[n0];
            const float bs1 = bsum[n0 + 1];
            float* p0 = sg + r0 * EROW + col;
            float* p1 = sg + (r0 + 8) * EROW + col;
            p0[0] = acc[mt][nt][0] + bs0; p0[1] = acc[mt][nt][1] + bs1;
            p1[0] = acc[mt][nt][2] + bs0; p1[1] = acc[mt][nt][3] + bs1;
        }
    }
    __syncthreads();

    // cell phase: 64 rows x 16 units, coalesced gmem
    const int ubase = bn >> 2;
#pragma unroll
    for (int it = 0; it < 8; it++) {
        const int idx = it * 128 + tid;          // 0..1023
        const int ml = idx >> 4;                 // 0..63
        const int ul = idx & 15;                 // 0..15
        const float4 g4 = *reinterpret_cast<const float4*>(sg + ml * EROW + ul * 4);

        const int m = bm + ml;
        const int u = ubase + ul;
        const int gix = m * HID + u;

        const float co = c[gix];
        const float si = 1.0f / (1.0f + expf(-g4.x));
        const float sf = 1.0f / (1.0f + expf(-g4.y));
        const float tg = tanhf(g4.z);
        const float so = 1.0f / (1.0f + expf(-g4.w));
        const float cn = sf * co + si * tg;
        const float hn = so * tanhf(cn);
        c[gix] = cn;
        hf_w[gix] = __float2half(hn);
        if (hlast != nullptr && m == SEQ - 1) hlast[u] = hn;
    }
}

// ---------------- setup kernels ----------------
__global__ void split_kernel(const float* __restrict__ src, __nv_bfloat16* __restrict__ hi,
                             __nv_bfloat16* __restrict__ lo, size_t n, float scale)
{
    const size_t i = (size_t)blockIdx.x * blockDim.x + threadIdx.x;
    if (i < n) {
        const float v = src[i] * scale;
        const __nv_bfloat16 h = __float2bfloat16(v);
        hi[i] = h;
        lo[i] = __float2bfloat16(v - __bfloat162float(h));
    }
}

// permute rows to gate-interleaved order (bf16 hi/lo): new_row = 4*unit + gate
__global__ void split_permute_w(const float* __restrict__ src, __nv_bfloat16* __restrict__ hi,
                                __nv_bfloat16* __restrict__ lo, int kshift)
{
    const size_t i = (size_t)blockIdx.x * blockDim.x + threadIdx.x;
    const int K = 1 << kshift;
    if (i < (size_t)GATES_N << kshift) {
        const int row = (int)(i >> kshift);
        const int k = (int)(i & (K - 1));
        const int nrow = ((row & 1023) << 2) | (row >> 10);
        const float v = src[i];
        const __nv_bfloat16 h = __float2bfloat16(v);
        hi[(size_t)nrow * K + k] = h;
        lo[(size_t)nrow * K + k] = __float2bfloat16(v - __bfloat162float(h));
    }
}

// permute rows to gate-interleaved order, single fp16
__global__ void permute_w16(const float* __restrict__ src, __half* __restrict__ dst, int kshift)
{
    const size_t i = (size_t)blockIdx.x * blockDim.x + threadIdx.x;
    const int K = 1 << kshift;
    if (i < (size_t)GATES_N << kshift) {
        const int row = (int)(i >> kshift);
        const int k = (int)(i & (K - 1));
        const int nrow = ((row & 1023) << 2) | (row >> 10);
        dst[(size_t)nrow * K + k] = __float2half(src[i]);
    }
}

__global__ void bias_combine(const float* __restrict__ b_ih, const float* __restrict__ b_hh,
                             float* __restrict__ bsum)
{
    const int i = blockIdx.x * blockDim.x + threadIdx.x;
    if (i < GATES_N) {
        const int ni = ((i & 1023) << 2) | (i >> 10);
        bsum[ni] = b_ih[i] + b_hh[i];
    }
}

__global__ void zero_state_kernel()
{
    const int i = blockIdx.x * blockDim.x + threadIdx.x;
    if (i < SEQ * HID) {
        g_hf[0][i] = __float2half(0.f);
        g_hf[1][i] = __float2half(0.f);
        g_c[i] = 0.f;
    }
}

__global__ __launch_bounds__(256)
void fc_kernel(const float* __restrict__ Hl, const float* __restrict__ Wfc,
               const float* __restrict__ bfc, float* __restrict__ out)
{
    __shared__ float hrow[HID];
    const int t = blockIdx.x;
    for (int k = threadIdx.x; k < HID; k += 256) hrow[k] = Hl[(size_t)t * HID + k];
    __syncthreads();
    for (int n = threadIdx.x; n < OUT_D; n += 256) {
        const float* w = Wfc + (size_t)n * HID;
        float s = 0.f;
#pragma unroll 8
        for (int k = 0; k < HID; k++) s = fmaf(hrow[k], w[k], s);
        out[(size_t)t * OUT_D + n] = s + bfc[n];
    }
}

// ---------------- launch ----------------
extern "C" void kernel_launch(void* const* d_in, const int* in_sizes, int n_in,
                              void* d_out, int out_size)
{
    const float* x     = (const float*)d_in[0];
    const float* w_ih1 = (const float*)d_in[1];
    const float* w_hh1 = (const float*)d_in[2];
    const float* b_ih1 = (const float*)d_in[3];
    const float* b_hh1 = (const float*)d_in[4];
    const float* w_ih2 = (const float*)d_in[5];
    const float* w_hh2 = (const float*)d_in[6];
    const float* b_ih2 = (const float*)d_in[7];
    const float* b_hh2 = (const float*)d_in[8];
    const float* w_fc  = (const float*)d_in[9];
    const float* b_fc  = (const float*)d_in[10];
    float* out = (float*)d_out;

    __nv_bfloat16 *xhi, *xlo, *wxh, *wxl;
    __half *whf, *hf;
    float *c, *hlast, *bias;
    cudaGetSymbolAddress((void**)&xhi, g_xhi);
    cudaGetSymbolAddress((void**)&xlo, g_xlo);
    cudaGetSymbolAddress((void**)&wxh, g_wxh);
    cudaGetSymbolAddress((void**)&wxl, g_wxl);
    cudaGetSymbolAddress((void**)&whf, g_whf);
    cudaGetSymbolAddress((void**)&hf,  g_hf);
    cudaGetSymbolAddress((void**)&c,     g_c);
    cudaGetSymbolAddress((void**)&hlast, g_hlast);
    cudaGetSymbolAddress((void**)&bias,  g_bias);

    cudaFuncSetAttribute(gemm_lstm, cudaFuncAttributeMaxDynamicSharedMemorySize, SMEM_DYN);

    const size_t nwx = (size_t)GATES_N * INPUT_D;
    const size_t nwh = (size_t)GATES_N * HID;
    const size_t nh  = (size_t)SEQ * HID;

    // setup: split x (*255); permute+split Wx (bf16); permute Whh (fp16); biases
    {
        const size_t nx = (size_t)STEPS * SEQ * INPUT_D;
        split_kernel<<<(unsigned)((nx + 255) / 256), 256>>>(x, xhi, xlo, nx, 255.0f);
        split_permute_w<<<(unsigned)((nwx + 255) / 256), 256>>>(w_ih1, wxh, wxl, 9);
        split_permute_w<<<(unsigned)((nwx + 255) / 256), 256>>>(w_ih2, wxh + nwx, wxl + nwx, 9);
        permute_w16<<<(unsigned)((nwh + 255) / 256), 256>>>(w_hh1, whf, 10);
        permute_w16<<<(unsigned)((nwh + 255) / 256), 256>>>(w_hh2, whf + nwh, 10);
        bias_combine<<<(GATES_N + 255) / 256, 256>>>(b_ih1, b_hh1, bias);
        bias_combine<<<(GATES_N + 255) / 256, 256>>>(b_ih2, b_hh2, bias + GATES_N);
    }
    zero_state_kernel<<<(SEQ * HID + 255) / 256, 256>>>();

    // PDL launch config
    cudaLaunchAttribute pdl_attr[1];
    pdl_attr[0].id = cudaLaunchAttributeProgrammaticStreamSerialization;
    pdl_attr[0].val.programmaticStreamSerializationAllowed = 1;

    cudaLaunchConfig_t gemm_cfg = {};
    gemm_cfg.gridDim = dim3(GATES_N / TILE_N, SEQ / TILE_M, 1);   // (64, 16) = 1024 CTAs
    gemm_cfg.blockDim = dim3(128, 1, 1);
    gemm_cfg.dynamicSmemBytes = SMEM_DYN;
    gemm_cfg.stream = 0;
    gemm_cfg.attrs = pdl_attr;
    gemm_cfg.numAttrs = 1;

    for (int t = 0; t < STEPS; ++t) {
        const __nv_bfloat16* xth = xhi + (size_t)t * SEQ * INPUT_D;
        const __nv_bfloat16* xtl = xlo + (size_t)t * SEQ * INPUT_D;
        float* hl = (float*)nullptr;

        // layer 1: reads hf[0], writes hf[1]
        cudaLaunchKernelEx(&gemm_cfg, gemm_lstm,
                           xth, xtl, (const __half*)hf,
                           (const __nv_bfloat16*)wxh, (const __nv_bfloat16*)wxl,
                           (const __half*)whf,
                           (const float*)bias, c,
                           hf + nh, hl);

        // layer 2: reads hf[1], writes hf[0]
        float* hl2 = hlast + (size_t)t * HID;
        cudaLaunchKernelEx(&gemm_cfg, gemm_lstm,
                           xth, xtl, (const __half*)(hf + nh),
                           (const __nv_bfloat16*)(wxh + nwx), (const __nv_bfloat16*)(wxl + nwx),
                           (const __half*)(whf + nwh),
                           (const float*)(bias + GATES_N), c,
                           hf, hl2);
    }

    fc_kernel<<<STEPS, 256>>>(hlast, w_fc, b_fc, out);
}